// round 1
// baseline (speedup 1.0000x reference)
#include <cuda_runtime.h>
#include <cuda_bf16.h>
#include <math.h>

// Problem constants
#define TKN   4096              // B*S tokens
#define DDIM  1024
#define FDIM  2048
#define NEXP  8
#define NASS  (TKN * 2)         // total assignments (top-2)

// ---------------------------------------------------------------------------
// Scratch (device globals; no dynamic allocation allowed)
// ---------------------------------------------------------------------------
__device__ int   g_counts[NEXP];
__device__ int   g_offsets[NEXP + 1];
__device__ int   g_cursor[NEXP];
__device__ int   g_rowTok[NASS];          // compact row -> token id
__device__ int   g_assignRow[NASS];       // (token,k) -> compact row
__device__ float g_probs[NASS];           // (token,k) -> prob
__device__ int   g_topE[NASS];            // (token,k) -> expert
__device__ float g_H[(size_t)NASS * FDIM];   // hidden after SwiGLU (64 MB)
__device__ float g_Y[(size_t)NASS * DDIM];   // per-assignment expert out (32 MB)

// ---------------------------------------------------------------------------
// Helpers
// ---------------------------------------------------------------------------
__device__ __forceinline__ float f2tf32(float f) {
    unsigned u;
    asm("cvt.rna.tf32.f32 %0, %1;" : "=r"(u) : "f"(f));
    return __uint_as_float(u);
}

__device__ __forceinline__ void mma_tf32(float* c, const unsigned* a,
                                         unsigned b0, unsigned b1) {
    asm volatile(
        "mma.sync.aligned.m16n8k8.row.col.f32.tf32.tf32.f32 "
        "{%0,%1,%2,%3}, {%4,%5,%6,%7}, {%8,%9}, {%0,%1,%2,%3};"
        : "+f"(c[0]), "+f"(c[1]), "+f"(c[2]), "+f"(c[3])
        : "r"(a[0]), "r"(a[1]), "r"(a[2]), "r"(a[3]), "r"(b0), "r"(b1));
}

// ---------------------------------------------------------------------------
// 0) Reset per-launch counters
// ---------------------------------------------------------------------------
__global__ void reset_kernel() {
    if (threadIdx.x < NEXP) g_counts[threadIdx.x] = 0;
}

// ---------------------------------------------------------------------------
// 1) Gating: scores = x . Wg[e]; top-2 + softmax; count per expert
//    One block per token, 8 warps = 8 experts.
// ---------------------------------------------------------------------------
__global__ __launch_bounds__(256) void gating_kernel(
    const float* __restrict__ x, const float* __restrict__ Wg) {
    int t = blockIdx.x;
    __shared__ float xs[DDIM];
    __shared__ float sc[NEXP];

    for (int i = threadIdx.x; i < DDIM; i += 256)
        xs[i] = x[(size_t)t * DDIM + i];
    __syncthreads();

    int w = threadIdx.x >> 5, lane = threadIdx.x & 31;
    const float* wg = Wg + (size_t)w * DDIM;
    float acc = 0.f;
    #pragma unroll 8
    for (int i = lane; i < DDIM; i += 32) acc += xs[i] * wg[i];
    #pragma unroll
    for (int o = 16; o; o >>= 1) acc += __shfl_xor_sync(0xFFFFFFFFu, acc, o);
    if (lane == 0) sc[w] = acc;
    __syncthreads();

    if (threadIdx.x == 0) {
        int e0 = 0; float s0 = sc[0];
        #pragma unroll
        for (int e = 1; e < NEXP; e++)
            if (sc[e] > s0) { s0 = sc[e]; e0 = e; }
        int e1 = -1; float s1 = -1e30f;
        #pragma unroll
        for (int e = 0; e < NEXP; e++)
            if (e != e0 && sc[e] > s1) { s1 = sc[e]; e1 = e; }
        float z = expf(s1 - s0);            // <= 1, safe
        float inv = 1.f / (1.f + z);
        g_topE[2 * t]     = e0;
        g_topE[2 * t + 1] = e1;
        g_probs[2 * t]     = inv;
        g_probs[2 * t + 1] = z * inv;
        atomicAdd(&g_counts[e0], 1);
        atomicAdd(&g_counts[e1], 1);
    }
}

// ---------------------------------------------------------------------------
// 2) Scan counts -> offsets, init cursors
// ---------------------------------------------------------------------------
__global__ void scan_kernel() {
    if (threadIdx.x == 0) {
        int o = 0;
        for (int e = 0; e < NEXP; e++) {
            g_offsets[e] = o;
            g_cursor[e]  = o;
            o += g_counts[e];
        }
        g_offsets[NEXP] = o;
    }
}

// ---------------------------------------------------------------------------
// 3) Scatter tokens into compacted per-expert row lists
// ---------------------------------------------------------------------------
__global__ void scatter_kernel() {
    int t = blockIdx.x * blockDim.x + threadIdx.x;
    if (t >= TKN) return;
    #pragma unroll
    for (int k = 0; k < 2; k++) {
        int e = g_topE[2 * t + k];
        int pos = atomicAdd(&g_cursor[e], 1);
        g_rowTok[pos] = t;
        g_assignRow[2 * t + k] = pos;
    }
}

// ---------------------------------------------------------------------------
// 4) GEMM1 + SwiGLU: H[r, f] = silu(x_r . W1[e,f]) * (x_r . W2[e,f])
//    Tile: BM=128 rows, BN=64 f-cols (both matrices), BK=32.
//    Block 256 threads = 8 warps (4 x 2); warp tile 32x32 per matrix.
// ---------------------------------------------------------------------------
__global__ __launch_bounds__(256) void gemm1_kernel(
    const float* __restrict__ x,
    const float* __restrict__ W1,
    const float* __restrict__ W2) {
    int e = blockIdx.z;
    int cnt = g_counts[e];
    int base = blockIdx.y * 128;
    if (base >= cnt) return;
    int off = g_offsets[e];
    int f0 = blockIdx.x * 64;

    int tid = threadIdx.x;
    int w = tid >> 5, lane = tid & 31;
    int wm = w >> 1, wn = w & 1;
    int g = lane >> 2, tig = lane & 3;

    __shared__ float As[128][36];   // stride 36 -> conflict-free frag loads
    __shared__ float B1s[64][36];
    __shared__ float B2s[64][36];
    __shared__ int   toks[128];

    if (tid < 128) {
        int r = base + tid;
        toks[tid] = (r < cnt) ? g_rowTok[off + r] : -1;
    }
    __syncthreads();

    float acc[2][2][4][4];
    #pragma unroll
    for (int m2 = 0; m2 < 2; m2++)
        #pragma unroll
        for (int mi = 0; mi < 2; mi++)
            #pragma unroll
            for (int ni = 0; ni < 4; ni++)
                #pragma unroll
                for (int q = 0; q < 4; q++) acc[m2][mi][ni][q] = 0.f;

    const float* W1e = W1 + ((size_t)e * FDIM + f0) * DDIM;
    const float* W2e = W2 + ((size_t)e * FDIM + f0) * DDIM;

    for (int k0 = 0; k0 < DDIM; k0 += 32) {
        // A tile: 128 x 32 (4 float4 per thread), gathered rows
        #pragma unroll
        for (int j = 0; j < 4; j++) {
            int lin = tid + j * 256;          // 0..1023
            int row = lin >> 3;
            int c4  = (lin & 7) * 4;
            int tok = toks[row];
            float4 v = make_float4(0.f, 0.f, 0.f, 0.f);
            if (tok >= 0)
                v = *(const float4*)(x + (size_t)tok * DDIM + k0 + c4);
            As[row][c4 + 0] = f2tf32(v.x);
            As[row][c4 + 1] = f2tf32(v.y);
            As[row][c4 + 2] = f2tf32(v.z);
            As[row][c4 + 3] = f2tf32(v.w);
        }
        // B tiles: 64 x 32 each (2 float4 per thread per matrix)
        #pragma unroll
        for (int j = 0; j < 2; j++) {
            int lin = tid + j * 256;          // 0..511
            int row = lin >> 3;
            int c4  = (lin & 7) * 4;
            float4 v1 = *(const float4*)(W1e + (size_t)row * DDIM + k0 + c4);
            float4 v2 = *(const float4*)(W2e + (size_t)row * DDIM + k0 + c4);
            B1s[row][c4 + 0] = f2tf32(v1.x);
            B1s[row][c4 + 1] = f2tf32(v1.y);
            B1s[row][c4 + 2] = f2tf32(v1.z);
            B1s[row][c4 + 3] = f2tf32(v1.w);
            B2s[row][c4 + 0] = f2tf32(v2.x);
            B2s[row][c4 + 1] = f2tf32(v2.y);
            B2s[row][c4 + 2] = f2tf32(v2.z);
            B2s[row][c4 + 3] = f2tf32(v2.w);
        }
        __syncthreads();

        #pragma unroll
        for (int kk = 0; kk < 4; kk++) {
            int ks = kk * 8;
            unsigned a[2][4];
            #pragma unroll
            for (int mi = 0; mi < 2; mi++) {
                int rm = wm * 32 + mi * 16;
                a[mi][0] = __float_as_uint(As[rm + g][ks + tig]);
                a[mi][1] = __float_as_uint(As[rm + g + 8][ks + tig]);
                a[mi][2] = __float_as_uint(As[rm + g][ks + tig + 4]);
                a[mi][3] = __float_as_uint(As[rm + g + 8][ks + tig + 4]);
            }
            #pragma unroll
            for (int ni = 0; ni < 4; ni++) {
                int rn = wn * 32 + ni * 8;
                unsigned b0 = __float_as_uint(B1s[rn + g][ks + tig]);
                unsigned b1 = __float_as_uint(B1s[rn + g][ks + tig + 4]);
                #pragma unroll
                for (int mi = 0; mi < 2; mi++)
                    mma_tf32(acc[0][mi][ni], a[mi], b0, b1);
                b0 = __float_as_uint(B2s[rn + g][ks + tig]);
                b1 = __float_as_uint(B2s[rn + g][ks + tig + 4]);
                #pragma unroll
                for (int mi = 0; mi < 2; mi++)
                    mma_tf32(acc[1][mi][ni], a[mi], b0, b1);
            }
        }
        __syncthreads();
    }

    // Epilogue: SwiGLU and store to g_H
    #pragma unroll
    for (int mi = 0; mi < 2; mi++) {
        #pragma unroll
        for (int ni = 0; ni < 4; ni++) {
            #pragma unroll
            for (int q = 0; q < 4; q++) {
                int row = wm * 32 + mi * 16 + g + ((q >= 2) ? 8 : 0);
                int col = wn * 32 + ni * 8 + tig * 2 + (q & 1);
                if (base + row < cnt) {
                    float h1 = acc[0][mi][ni][q];
                    float h2 = acc[1][mi][ni][q];
                    float s = h1 / (1.f + expf(-h1));   // silu
                    g_H[(size_t)(off + base + row) * FDIM + f0 + col] = s * h2;
                }
            }
        }
    }
}

// ---------------------------------------------------------------------------
// 5) GEMM2: Y[r, d] = H[r, :] . W3[e, d, :]
//    Tile: BM=128 rows, BN=128 d-cols, BK=32. 8 warps (4x2); warp tile 32x64.
// ---------------------------------------------------------------------------
__global__ __launch_bounds__(256) void gemm2_kernel(const float* __restrict__ W3) {
    int e = blockIdx.z;
    int cnt = g_counts[e];
    int base = blockIdx.y * 128;
    if (base >= cnt) return;
    int off = g_offsets[e];
    int d0 = blockIdx.x * 128;

    int tid = threadIdx.x;
    int w = tid >> 5, lane = tid & 31;
    int wm = w >> 1, wn = w & 1;
    int g = lane >> 2, tig = lane & 3;

    __shared__ float As[128][36];
    __shared__ float Bs[128][36];

    float acc[2][8][4];
    #pragma unroll
    for (int mi = 0; mi < 2; mi++)
        #pragma unroll
        for (int ni = 0; ni < 8; ni++)
            #pragma unroll
            for (int q = 0; q < 4; q++) acc[mi][ni][q] = 0.f;

    const float* W3e = W3 + ((size_t)e * DDIM + d0) * FDIM;

    for (int k0 = 0; k0 < FDIM; k0 += 32) {
        // A tile: g_H rows (contiguous, already compacted)
        #pragma unroll
        for (int j = 0; j < 4; j++) {
            int lin = tid + j * 256;
            int row = lin >> 3;
            int c4  = (lin & 7) * 4;
            float4 v = make_float4(0.f, 0.f, 0.f, 0.f);
            if (base + row < cnt)
                v = *(const float4*)(g_H + (size_t)(off + base + row) * FDIM + k0 + c4);
            As[row][c4 + 0] = f2tf32(v.x);
            As[row][c4 + 1] = f2tf32(v.y);
            As[row][c4 + 2] = f2tf32(v.z);
            As[row][c4 + 3] = f2tf32(v.w);
        }
        // B tile: 128 x 32 of W3[e]
        #pragma unroll
        for (int j = 0; j < 4; j++) {
            int lin = tid + j * 256;
            int row = lin >> 3;
            int c4  = (lin & 7) * 4;
            float4 v = *(const float4*)(W3e + (size_t)row * FDIM + k0 + c4);
            Bs[row][c4 + 0] = f2tf32(v.x);
            Bs[row][c4 + 1] = f2tf32(v.y);
            Bs[row][c4 + 2] = f2tf32(v.z);
            Bs[row][c4 + 3] = f2tf32(v.w);
        }
        __syncthreads();

        #pragma unroll
        for (int kk = 0; kk < 4; kk++) {
            int ks = kk * 8;
            unsigned a[2][4];
            #pragma unroll
            for (int mi = 0; mi < 2; mi++) {
                int rm = wm * 32 + mi * 16;
                a[mi][0] = __float_as_uint(As[rm + g][ks + tig]);
                a[mi][1] = __float_as_uint(As[rm + g + 8][ks + tig]);
                a[mi][2] = __float_as_uint(As[rm + g][ks + tig + 4]);
                a[mi][3] = __float_as_uint(As[rm + g + 8][ks + tig + 4]);
            }
            #pragma unroll
            for (int ni = 0; ni < 8; ni++) {
                int rn = wn * 64 + ni * 8;
                unsigned b0 = __float_as_uint(Bs[rn + g][ks + tig]);
                unsigned b1 = __float_as_uint(Bs[rn + g][ks + tig + 4]);
                #pragma unroll
                for (int mi = 0; mi < 2; mi++)
                    mma_tf32(acc[mi][ni], a[mi], b0, b1);
            }
        }
        __syncthreads();
    }

    #pragma unroll
    for (int mi = 0; mi < 2; mi++) {
        #pragma unroll
        for (int ni = 0; ni < 8; ni++) {
            #pragma unroll
            for (int q = 0; q < 4; q++) {
                int row = wm * 32 + mi * 16 + g + ((q >= 2) ? 8 : 0);
                int col = wn * 64 + ni * 8 + tig * 2 + (q & 1);
                if (base + row < cnt)
                    g_Y[(size_t)(off + base + row) * DDIM + d0 + col] = acc[mi][ni][q];
            }
        }
    }
}

// ---------------------------------------------------------------------------
// 6) Combine: out[t, :] = p0 * Y[row0, :] + p1 * Y[row1, :]
// ---------------------------------------------------------------------------
__global__ __launch_bounds__(256) void combine_kernel(float* __restrict__ out) {
    int t = blockIdx.x;
    float p0 = g_probs[2 * t];
    float p1 = g_probs[2 * t + 1];
    const float4* y0 = (const float4*)(g_Y + (size_t)g_assignRow[2 * t] * DDIM);
    const float4* y1 = (const float4*)(g_Y + (size_t)g_assignRow[2 * t + 1] * DDIM);
    float4* o = (float4*)(out + (size_t)t * DDIM);
    int i = threadIdx.x;            // 256 threads x float4 = 1024 floats
    float4 a = y0[i], b = y1[i];
    o[i] = make_float4(p0 * a.x + p1 * b.x,
                       p0 * a.y + p1 * b.y,
                       p0 * a.z + p1 * b.z,
                       p0 * a.w + p1 * b.w);
}

// ---------------------------------------------------------------------------
// Entry point
// ---------------------------------------------------------------------------
extern "C" void kernel_launch(void* const* d_in, const int* in_sizes, int n_in,
                              void* d_out, int out_size) {
    (void)in_sizes; (void)n_in; (void)out_size;
    const float* x  = (const float*)d_in[0];
    const float* Wg = (const float*)d_in[1];
    const float* W1 = (const float*)d_in[2];
    const float* W2 = (const float*)d_in[3];
    const float* W3 = (const float*)d_in[4];
    float* out = (float*)d_out;

    reset_kernel<<<1, 32>>>();
    gating_kernel<<<TKN, 256>>>(x, Wg);
    scan_kernel<<<1, 1>>>();
    scatter_kernel<<<TKN / 256, 256>>>();
    gemm1_kernel<<<dim3(FDIM / 64, TKN / 128, NEXP), 256>>>(x, W1, W2);
    gemm2_kernel<<<dim3(DDIM / 128, TKN / 128, NEXP), 256>>>(W3);
    combine_kernel<<<TKN, 256>>>(out);
}

// round 3
// speedup vs baseline: 2.0416x; 2.0416x over previous
#include <cuda_runtime.h>
#include <cuda_fp16.h>
#include <cstdint>
#include <math.h>

// Problem constants
#define TKN   4096
#define DDIM  1024
#define FDIM  2048
#define NEXP  8
#define NASS  (TKN * 2)

// ---------------------------------------------------------------------------
// Scratch (device globals)
// ---------------------------------------------------------------------------
__device__ int   g_counts[NEXP];
__device__ int   g_offsets[NEXP + 1];
__device__ int   g_cursor[NEXP];
__device__ int   g_rowTok[NASS];
__device__ int   g_assignRow[NASS];
__device__ float g_probs[NASS];
__device__ int   g_topE[NASS];

__device__ __align__(16) __half g_xh[(size_t)TKN * DDIM];
__device__ __align__(16) __half g_W1h[(size_t)NEXP * FDIM * DDIM];
__device__ __align__(16) __half g_W2h[(size_t)NEXP * FDIM * DDIM];
__device__ __align__(16) __half g_W3h[(size_t)NEXP * DDIM * FDIM];
__device__ __align__(16) __half g_Hh[(size_t)NASS * FDIM];
__device__ __align__(16) float  g_Y[(size_t)NASS * DDIM];

// ---------------------------------------------------------------------------
// Helpers
// ---------------------------------------------------------------------------
__device__ __forceinline__ uint32_t smem_u32(const void* p) {
    uint32_t a;
    asm("{ .reg .u64 t; cvta.to.shared.u64 t, %1; cvt.u32.u64 %0, t; }" : "=r"(a) : "l"(p));
    return a;
}
__device__ __forceinline__ void cp16(void* dst, const void* src, int zfill) {
    uint32_t d = smem_u32(dst);
    asm volatile("cp.async.cg.shared.global [%0], [%1], 16, %2;"
                 :: "r"(d), "l"(src), "r"(zfill) : "memory");
}
#define CP_COMMIT() asm volatile("cp.async.commit_group;" ::: "memory")
#define CP_WAIT(n)  asm volatile("cp.async.wait_group %0;" :: "n"(n) : "memory")

__device__ __forceinline__ void mma_f16(float* c, const uint32_t* a,
                                        uint32_t b0, uint32_t b1) {
    asm volatile(
        "mma.sync.aligned.m16n8k16.row.col.f32.f16.f16.f32 "
        "{%0,%1,%2,%3}, {%4,%5,%6,%7}, {%8,%9}, {%0,%1,%2,%3};"
        : "+f"(c[0]), "+f"(c[1]), "+f"(c[2]), "+f"(c[3])
        : "r"(a[0]), "r"(a[1]), "r"(a[2]), "r"(a[3]), "r"(b0), "r"(b1));
}

// ---------------------------------------------------------------------------
// fp32 -> fp16 conversion (which: 0=x, 1=W1, 2=W2, 3=W3)
// ---------------------------------------------------------------------------
__global__ __launch_bounds__(256) void f2h_kernel(
    const float* __restrict__ s, int which, int n4) {
    int i = blockIdx.x * blockDim.x + threadIdx.x;
    if (i >= n4) return;
    __half* d = (which == 0) ? g_xh : (which == 1) ? g_W1h
              : (which == 2) ? g_W2h : g_W3h;
    float4 v = ((const float4*)s)[i];
    __half2 h0 = __floats2half2_rn(v.x, v.y);
    __half2 h1 = __floats2half2_rn(v.z, v.w);
    ((__half2*)d)[2 * i]     = h0;
    ((__half2*)d)[2 * i + 1] = h1;
}

// ---------------------------------------------------------------------------
// Routing kernels
// ---------------------------------------------------------------------------
__global__ void reset_kernel() {
    if (threadIdx.x < NEXP) g_counts[threadIdx.x] = 0;
}

__global__ __launch_bounds__(256) void gating_kernel(
    const float* __restrict__ x, const float* __restrict__ Wg) {
    int t = blockIdx.x;
    __shared__ float xs[DDIM];
    __shared__ float sc[NEXP];
    for (int i = threadIdx.x; i < DDIM; i += 256)
        xs[i] = x[(size_t)t * DDIM + i];
    __syncthreads();
    int w = threadIdx.x >> 5, lane = threadIdx.x & 31;
    const float* wg = Wg + (size_t)w * DDIM;
    float acc = 0.f;
    #pragma unroll 8
    for (int i = lane; i < DDIM; i += 32) acc += xs[i] * wg[i];
    #pragma unroll
    for (int o = 16; o; o >>= 1) acc += __shfl_xor_sync(0xFFFFFFFFu, acc, o);
    if (lane == 0) sc[w] = acc;
    __syncthreads();
    if (threadIdx.x == 0) {
        int e0 = 0; float s0 = sc[0];
        #pragma unroll
        for (int e = 1; e < NEXP; e++)
            if (sc[e] > s0) { s0 = sc[e]; e0 = e; }
        int e1 = -1; float s1 = -1e30f;
        #pragma unroll
        for (int e = 0; e < NEXP; e++)
            if (e != e0 && sc[e] > s1) { s1 = sc[e]; e1 = e; }
        float z = expf(s1 - s0);
        float inv = 1.f / (1.f + z);
        g_topE[2 * t] = e0;  g_topE[2 * t + 1] = e1;
        g_probs[2 * t] = inv; g_probs[2 * t + 1] = z * inv;
        atomicAdd(&g_counts[e0], 1);
        atomicAdd(&g_counts[e1], 1);
    }
}

__global__ void scan_kernel() {
    if (threadIdx.x == 0) {
        int o = 0;
        for (int e = 0; e < NEXP; e++) {
            g_offsets[e] = o; g_cursor[e] = o; o += g_counts[e];
        }
        g_offsets[NEXP] = o;
    }
}

__global__ void scatter_kernel() {
    int t = blockIdx.x * blockDim.x + threadIdx.x;
    if (t >= TKN) return;
    #pragma unroll
    for (int k = 0; k < 2; k++) {
        int e = g_topE[2 * t + k];
        int pos = atomicAdd(&g_cursor[e], 1);
        g_rowTok[pos] = t;
        g_assignRow[2 * t + k] = pos;
    }
}

__global__ __launch_bounds__(256) void combine_kernel(float* __restrict__ out) {
    int t = blockIdx.x;
    float p0 = g_probs[2 * t], p1 = g_probs[2 * t + 1];
    const float4* y0 = (const float4*)(g_Y + (size_t)g_assignRow[2 * t] * DDIM);
    const float4* y1 = (const float4*)(g_Y + (size_t)g_assignRow[2 * t + 1] * DDIM);
    float4* o = (float4*)(out + (size_t)t * DDIM);
    int i = threadIdx.x;
    float4 a = y0[i], b = y1[i];
    o[i] = make_float4(p0 * a.x + p1 * b.x, p0 * a.y + p1 * b.y,
                       p0 * a.z + p1 * b.z, p0 * a.w + p1 * b.w);
}

// ---------------------------------------------------------------------------
// GEMM tile geometry (shared by both GEMMs)
//   K_TILE = 32 halves, rows padded to stride 40 halves (80 bytes).
//   A tile 128 rows (10240 B/stage), B tile 256 rows (20480 B/stage), 3 stages.
// ---------------------------------------------------------------------------
#define RSTR    40                 // halves per smem row (32 + 8 pad)
#define RSTRB   80                 // bytes per smem row
#define RSTRU   20                 // u32 per smem row
#define G_SA    (128 * RSTRB)      // 10240
#define G_SB    (256 * RSTRB)      // 20480
#define SMEM_DYN (3 * (G_SA + G_SB))   // 92160

// ---------------------------------------------------------------------------
// GEMM1 + SwiGLU: H[r,f] = silu(x_r.W1[e,f]) * (x_r.W2[e,f])
//   Block: 512 thr (16 warps, 4x4). BM=128 rows, BF=128 f-cols, both matrices.
//   B smem rows 0-127 = W1 slice, 128-255 = W2 slice.
// ---------------------------------------------------------------------------
__global__ __launch_bounds__(512, 1)
void gemm1_kernel() {
    int e = blockIdx.z;
    int cnt = g_counts[e];
    int base = blockIdx.y * 128;
    if (base >= cnt) return;
    int off = g_offsets[e];
    int f0 = blockIdx.x * 128;

    extern __shared__ char sm[];
    __shared__ int toks[128];
    int tid = threadIdx.x;
    if (tid < 128)
        toks[tid] = (base + tid < cnt) ? g_rowTok[off + base + tid] : -1;
    __syncthreads();

    const __half* W1e = g_W1h + ((size_t)e * FDIM + f0) * DDIM;
    const __half* W2e = g_W2h + ((size_t)e * FDIM + f0) * DDIM;

    int w = tid >> 5, lane = tid & 31;
    int wm = w >> 2, wn = w & 3;          // wm: row quad, wn: f quad
    int g = lane >> 2, tig = lane & 3;

    float acc1[2][4][4], acc2[2][4][4];
    #pragma unroll
    for (int mi = 0; mi < 2; mi++)
        #pragma unroll
        for (int ni = 0; ni < 4; ni++)
            #pragma unroll
            for (int q = 0; q < 4; q++) { acc1[mi][ni][q] = 0.f; acc2[mi][ni][q] = 0.f; }

    const int NKT = DDIM / 32;   // 32

    // loader: stage s, k-offset k0
    auto load_stage = [&](int s, int k0) {
        char* smA = sm + s * G_SA;
        char* smB = sm + 3 * G_SA + s * G_SB;
        {   // A: 128 rows x 32h, 512 chunks of 16B
            int row = tid >> 2, q = tid & 3;
            int tok = toks[row];
            const __half* src = g_xh + (size_t)(tok >= 0 ? tok : 0) * DDIM + k0 + q * 8;
            cp16(smA + row * RSTRB + q * 16, src, tok >= 0 ? 16 : 0);
        }
        #pragma unroll
        for (int j = 0; j < 2; j++) {   // B: 256 rows x 32h
            int slot = tid + j * 512;
            int r = slot >> 2, q = slot & 3;
            int mat = r >> 7, rw = r & 127;
            const __half* src = (mat ? W2e : W1e) + (size_t)rw * DDIM + k0 + q * 8;
            cp16(smB + r * RSTRB + q * 16, src, 16);
        }
    };

    load_stage(0, 0);  CP_COMMIT();
    load_stage(1, 32); CP_COMMIT();

    for (int kt = 0; kt < NKT; kt++) {
        if (kt + 2 < NKT) { load_stage((kt + 2) % 3, (kt + 2) * 32); CP_COMMIT(); }
        if (kt + 2 < NKT) CP_WAIT(2);
        else if (kt + 1 < NKT) CP_WAIT(1);
        else CP_WAIT(0);
        __syncthreads();

        int s = kt % 3;
        const uint32_t* pA = (const uint32_t*)(sm + s * G_SA);
        const uint32_t* pB = (const uint32_t*)(sm + 3 * G_SA + s * G_SB);

        #pragma unroll
        for (int ks = 0; ks < 2; ks++) {
            int kh = ks * 8 + tig;
            uint32_t a[2][4];
            #pragma unroll
            for (int mi = 0; mi < 2; mi++) {
                int rm = wm * 32 + mi * 16 + g;
                a[mi][0] = pA[rm * RSTRU + kh];
                a[mi][1] = pA[(rm + 8) * RSTRU + kh];
                a[mi][2] = pA[rm * RSTRU + kh + 4];
                a[mi][3] = pA[(rm + 8) * RSTRU + kh + 4];
            }
            #pragma unroll
            for (int ni = 0; ni < 4; ni++) {
                int n1 = wn * 32 + ni * 8 + g;
                uint32_t b10 = pB[n1 * RSTRU + kh];
                uint32_t b11 = pB[n1 * RSTRU + kh + 4];
                uint32_t b20 = pB[(n1 + 128) * RSTRU + kh];
                uint32_t b21 = pB[(n1 + 128) * RSTRU + kh + 4];
                #pragma unroll
                for (int mi = 0; mi < 2; mi++) {
                    mma_f16(acc1[mi][ni], a[mi], b10, b11);
                    mma_f16(acc2[mi][ni], a[mi], b20, b21);
                }
            }
        }
        __syncthreads();
    }

    // Epilogue: SwiGLU -> Hh (fp16)
    #pragma unroll
    for (int mi = 0; mi < 2; mi++) {
        int r0 = base + wm * 32 + mi * 16 + g;
        #pragma unroll
        for (int ni = 0; ni < 4; ni++) {
            int col = f0 + wn * 32 + ni * 8 + tig * 2;
            #pragma unroll
            for (int half = 0; half < 2; half++) {
                int row = r0 + half * 8;
                if (row < cnt) {
                    float h1a = acc1[mi][ni][half * 2 + 0];
                    float h1b = acc1[mi][ni][half * 2 + 1];
                    float h2a = acc2[mi][ni][half * 2 + 0];
                    float h2b = acc2[mi][ni][half * 2 + 1];
                    float oa = h1a / (1.f + expf(-h1a)) * h2a;
                    float ob = h1b / (1.f + expf(-h1b)) * h2b;
                    *(__half2*)(g_Hh + (size_t)(off + row) * FDIM + col) =
                        __floats2half2_rn(oa, ob);
                }
            }
        }
    }
}

// ---------------------------------------------------------------------------
// GEMM2: Y[r,d] = H[r,:].W3[e,d,:]
//   Block: 512 thr (16 warps, 4x4). BM=128 rows, BN=256 d-cols.
// ---------------------------------------------------------------------------
__global__ __launch_bounds__(512, 1)
void gemm2_kernel() {
    int e = blockIdx.z;
    int cnt = g_counts[e];
    int base = blockIdx.y * 128;
    if (base >= cnt) return;
    int off = g_offsets[e];
    int d0 = blockIdx.x * 256;

    extern __shared__ char sm[];
    int tid = threadIdx.x;

    const __half* W3e = g_W3h + ((size_t)e * DDIM + d0) * FDIM;
    const __half* Ab  = g_Hh + (size_t)(off + base) * FDIM;
    int arows = cnt - base;

    int w = tid >> 5, lane = tid & 31;
    int wm = w >> 2, wn = w & 3;
    int g = lane >> 2, tig = lane & 3;

    float acc[2][8][4];
    #pragma unroll
    for (int mi = 0; mi < 2; mi++)
        #pragma unroll
        for (int ni = 0; ni < 8; ni++)
            #pragma unroll
            for (int q = 0; q < 4; q++) acc[mi][ni][q] = 0.f;

    const int NKT = FDIM / 32;   // 64

    auto load_stage = [&](int s, int k0) {
        char* smA = sm + s * G_SA;
        char* smB = sm + 3 * G_SA + s * G_SB;
        {
            int row = tid >> 2, q = tid & 3;
            const __half* src = Ab + (size_t)(row < arows ? row : 0) * FDIM + k0 + q * 8;
            cp16(smA + row * RSTRB + q * 16, src, row < arows ? 16 : 0);
        }
        #pragma unroll
        for (int j = 0; j < 2; j++) {
            int slot = tid + j * 512;
            int r = slot >> 2, q = slot & 3;
            const __half* src = W3e + (size_t)r * FDIM + k0 + q * 8;
            cp16(smB + r * RSTRB + q * 16, src, 16);
        }
    };

    load_stage(0, 0);  CP_COMMIT();
    load_stage(1, 32); CP_COMMIT();

    for (int kt = 0; kt < NKT; kt++) {
        if (kt + 2 < NKT) { load_stage((kt + 2) % 3, (kt + 2) * 32); CP_COMMIT(); }
        if (kt + 2 < NKT) CP_WAIT(2);
        else if (kt + 1 < NKT) CP_WAIT(1);
        else CP_WAIT(0);
        __syncthreads();

        int s = kt % 3;
        const uint32_t* pA = (const uint32_t*)(sm + s * G_SA);
        const uint32_t* pB = (const uint32_t*)(sm + 3 * G_SA + s * G_SB);

        #pragma unroll
        for (int ks = 0; ks < 2; ks++) {
            int kh = ks * 8 + tig;
            uint32_t a[2][4];
            #pragma unroll
            for (int mi = 0; mi < 2; mi++) {
                int rm = wm * 32 + mi * 16 + g;
                a[mi][0] = pA[rm * RSTRU + kh];
                a[mi][1] = pA[(rm + 8) * RSTRU + kh];
                a[mi][2] = pA[rm * RSTRU + kh + 4];
                a[mi][3] = pA[(rm + 8) * RSTRU + kh + 4];
            }
            #pragma unroll
            for (int ni = 0; ni < 8; ni++) {
                int n0 = wn * 64 + ni * 8 + g;
                uint32_t b0 = pB[n0 * RSTRU + kh];
                uint32_t b1 = pB[n0 * RSTRU + kh + 4];
                #pragma unroll
                for (int mi = 0; mi < 2; mi++)
                    mma_f16(acc[mi][ni], a[mi], b0, b1);
            }
        }
        __syncthreads();
    }

    #pragma unroll
    for (int mi = 0; mi < 2; mi++) {
        int r0 = base + wm * 32 + mi * 16 + g;
        #pragma unroll
        for (int ni = 0; ni < 8; ni++) {
            int col = d0 + wn * 64 + ni * 8 + tig * 2;
            #pragma unroll
            for (int half = 0; half < 2; half++) {
                int row = r0 + half * 8;
                if (row < cnt) {
                    *(float2*)(g_Y + (size_t)(off + row) * DDIM + col) =
                        make_float2(acc[mi][ni][half * 2 + 0],
                                    acc[mi][ni][half * 2 + 1]);
                }
            }
        }
    }
}

// ---------------------------------------------------------------------------
// Entry point
// ---------------------------------------------------------------------------
extern "C" void kernel_launch(void* const* d_in, const int* in_sizes, int n_in,
                              void* d_out, int out_size) {
    (void)in_sizes; (void)n_in; (void)out_size;
    const float* x  = (const float*)d_in[0];
    const float* Wg = (const float*)d_in[1];
    const float* W1 = (const float*)d_in[2];
    const float* W2 = (const float*)d_in[3];
    const float* W3 = (const float*)d_in[4];
    float* out = (float*)d_out;

    static int attr_done = 0;
    if (!attr_done) {
        cudaFuncSetAttribute(gemm1_kernel, cudaFuncAttributeMaxDynamicSharedMemorySize, SMEM_DYN);
        cudaFuncSetAttribute(gemm2_kernel, cudaFuncAttributeMaxDynamicSharedMemorySize, SMEM_DYN);
        attr_done = 1;
    }

    reset_kernel<<<1, 32>>>();

    // fp32 -> fp16 conversions
    f2h_kernel<<<(TKN * DDIM / 4 + 255) / 256, 256>>>(x, 0, TKN * DDIM / 4);
    int wn4 = NEXP * FDIM * DDIM / 4;
    f2h_kernel<<<(wn4 + 255) / 256, 256>>>(W1, 1, wn4);
    f2h_kernel<<<(wn4 + 255) / 256, 256>>>(W2, 2, wn4);
    f2h_kernel<<<(wn4 + 255) / 256, 256>>>(W3, 3, wn4);

    gating_kernel<<<TKN, 256>>>(x, Wg);
    scan_kernel<<<1, 1>>>();
    scatter_kernel<<<TKN / 256, 256>>>();

    gemm1_kernel<<<dim3(FDIM / 128, TKN / 128, NEXP), 512, SMEM_DYN>>>();
    gemm2_kernel<<<dim3(DDIM / 256, TKN / 128, NEXP), 512, SMEM_DYN>>>();

    combine_kernel<<<TKN, 256>>>(out);
}

// round 4
// speedup vs baseline: 2.2121x; 1.0835x over previous
#include <cuda_runtime.h>
#include <cuda_fp16.h>
#include <cstdint>
#include <math.h>

// Problem constants
#define TKN   4096
#define DDIM  1024
#define FDIM  2048
#define NEXP  8
#define NASS  (TKN * 2)

// ---------------------------------------------------------------------------
// Scratch (device globals)
// ---------------------------------------------------------------------------
__device__ int   g_counts[NEXP];
__device__ int   g_offsets[NEXP + 1];
__device__ int   g_cursor[NEXP];
__device__ int   g_rowTok[NASS];
__device__ int   g_assignRow[NASS];
__device__ float g_probs[NASS];
__device__ int   g_topE[NASS];

__device__ __align__(16) __half g_xh[(size_t)TKN * DDIM];
__device__ __align__(16) __half g_W1h[(size_t)NEXP * FDIM * DDIM];
__device__ __align__(16) __half g_W2h[(size_t)NEXP * FDIM * DDIM];
__device__ __align__(16) __half g_W3h[(size_t)NEXP * DDIM * FDIM];
__device__ __align__(16) __half g_Hh[(size_t)NASS * FDIM];
__device__ __align__(16) float  g_Y[(size_t)NASS * DDIM];

// ---------------------------------------------------------------------------
// Helpers
// ---------------------------------------------------------------------------
__device__ __forceinline__ uint32_t smem_u32(const void* p) {
    uint32_t a;
    asm("{ .reg .u64 t; cvta.to.shared.u64 t, %1; cvt.u32.u64 %0, t; }" : "=r"(a) : "l"(p));
    return a;
}
__device__ __forceinline__ void cp16(void* dst, const void* src, int zfill) {
    uint32_t d = smem_u32(dst);
    asm volatile("cp.async.cg.shared.global [%0], [%1], 16, %2;"
                 :: "r"(d), "l"(src), "r"(zfill) : "memory");
}
#define CP_COMMIT() asm volatile("cp.async.commit_group;" ::: "memory")
#define CP_WAIT(n)  asm volatile("cp.async.wait_group %0;" :: "n"(n) : "memory")

__device__ __forceinline__ void mma_f16(float* c, const uint32_t* a,
                                        uint32_t b0, uint32_t b1) {
    asm volatile(
        "mma.sync.aligned.m16n8k16.row.col.f32.f16.f16.f32 "
        "{%0,%1,%2,%3}, {%4,%5,%6,%7}, {%8,%9}, {%0,%1,%2,%3};"
        : "+f"(c[0]), "+f"(c[1]), "+f"(c[2]), "+f"(c[3])
        : "r"(a[0]), "r"(a[1]), "r"(a[2]), "r"(a[3]), "r"(b0), "r"(b1));
}
__device__ __forceinline__ void ldsm4(uint32_t* r, uint32_t a) {
    asm volatile("ldmatrix.sync.aligned.m8n8.x4.shared.b16 {%0,%1,%2,%3}, [%4];"
                 : "=r"(r[0]), "=r"(r[1]), "=r"(r[2]), "=r"(r[3]) : "r"(a));
}
__device__ __forceinline__ void ldsm2(uint32_t* r, uint32_t a) {
    asm volatile("ldmatrix.sync.aligned.m8n8.x2.shared.b16 {%0,%1}, [%2];"
                 : "=r"(r[0]), "=r"(r[1]) : "r"(a));
}

// ---------------------------------------------------------------------------
// Fused fp32->fp16 convert for x, W1, W2, W3 + zero routing counters
// ---------------------------------------------------------------------------
#define X4 (TKN * DDIM / 4)
#define W4 (NEXP * FDIM * DDIM / 4)
#define CVT_TOTAL (X4 + 3 * W4)

__global__ __launch_bounds__(256) void convert_kernel(
    const float* __restrict__ x, const float* __restrict__ W1,
    const float* __restrict__ W2, const float* __restrict__ W3) {
    if (blockIdx.x == 0 && threadIdx.x < NEXP) {
        g_counts[threadIdx.x] = 0;
        g_cursor[threadIdx.x] = 0;
    }
    long i = (long)blockIdx.x * 256 + threadIdx.x;
    const float* s; __half* d; long j;
    if (i < X4)                { s = x;  d = g_xh;  j = i; }
    else if (i < X4 + W4)      { s = W1; d = g_W1h; j = i - X4; }
    else if (i < X4 + 2L * W4) { s = W2; d = g_W2h; j = i - X4 - W4; }
    else if (i < CVT_TOTAL)    { s = W3; d = g_W3h; j = i - X4 - 2L * W4; }
    else return;
    float4 v = ((const float4*)s)[j];
    ((__half2*)d)[2 * j]     = __floats2half2_rn(v.x, v.y);
    ((__half2*)d)[2 * j + 1] = __floats2half2_rn(v.z, v.w);
}

// ---------------------------------------------------------------------------
// Gating: top-2 + softmax + per-expert counts
// ---------------------------------------------------------------------------
__global__ __launch_bounds__(256) void gating_kernel(
    const float* __restrict__ x, const float* __restrict__ Wg) {
    int t = blockIdx.x;
    __shared__ float xs[DDIM];
    __shared__ float sc[NEXP];
    for (int i = threadIdx.x; i < DDIM; i += 256)
        xs[i] = x[(size_t)t * DDIM + i];
    __syncthreads();
    int w = threadIdx.x >> 5, lane = threadIdx.x & 31;
    const float* wg = Wg + (size_t)w * DDIM;
    float acc = 0.f;
    #pragma unroll 8
    for (int i = lane; i < DDIM; i += 32) acc += xs[i] * wg[i];
    #pragma unroll
    for (int o = 16; o; o >>= 1) acc += __shfl_xor_sync(0xFFFFFFFFu, acc, o);
    if (lane == 0) sc[w] = acc;
    __syncthreads();
    if (threadIdx.x == 0) {
        int e0 = 0; float s0 = sc[0];
        #pragma unroll
        for (int e = 1; e < NEXP; e++)
            if (sc[e] > s0) { s0 = sc[e]; e0 = e; }
        int e1 = -1; float s1 = -1e30f;
        #pragma unroll
        for (int e = 0; e < NEXP; e++)
            if (e != e0 && sc[e] > s1) { s1 = sc[e]; e1 = e; }
        float z = expf(s1 - s0);
        float inv = 1.f / (1.f + z);
        g_topE[2 * t] = e0;  g_topE[2 * t + 1] = e1;
        g_probs[2 * t] = inv; g_probs[2 * t + 1] = z * inv;
        atomicAdd(&g_counts[e0], 1);
        atomicAdd(&g_counts[e1], 1);
    }
}

// ---------------------------------------------------------------------------
// Scatter (with local scan of the 8 expert counts)
// ---------------------------------------------------------------------------
__global__ __launch_bounds__(256) void scatter_kernel() {
    __shared__ int soff[NEXP];
    if (threadIdx.x < NEXP) {
        int o = 0;
        for (int e = 0; e < threadIdx.x; e++) o += g_counts[e];
        soff[threadIdx.x] = o;
        if (blockIdx.x == 0) {
            g_offsets[threadIdx.x] = o;
            if (threadIdx.x == NEXP - 1) g_offsets[NEXP] = o + g_counts[NEXP - 1];
        }
    }
    __syncthreads();
    int t = blockIdx.x * blockDim.x + threadIdx.x;
    if (t >= TKN) return;
    #pragma unroll
    for (int k = 0; k < 2; k++) {
        int e = g_topE[2 * t + k];
        int pos = soff[e] + atomicAdd(&g_cursor[e], 1);
        g_rowTok[pos] = t;
        g_assignRow[2 * t + k] = pos;
    }
}

__global__ __launch_bounds__(256) void combine_kernel(float* __restrict__ out) {
    int t = blockIdx.x;
    float p0 = g_probs[2 * t], p1 = g_probs[2 * t + 1];
    const float4* y0 = (const float4*)(g_Y + (size_t)g_assignRow[2 * t] * DDIM);
    const float4* y1 = (const float4*)(g_Y + (size_t)g_assignRow[2 * t + 1] * DDIM);
    float4* o = (float4*)(out + (size_t)t * DDIM);
    int i = threadIdx.x;
    float4 a = y0[i], b = y1[i];
    o[i] = make_float4(p0 * a.x + p1 * b.x, p0 * a.y + p1 * b.y,
                       p0 * a.z + p1 * b.z, p0 * a.w + p1 * b.w);
}

// ---------------------------------------------------------------------------
// GEMM tile geometry: K_TILE=32 halves, row stride 40 halves (80 B), 3 stages
// ---------------------------------------------------------------------------
#define RSTRB   80
#define G_SA    (128 * RSTRB)
#define G_SB    (256 * RSTRB)
#define SMEM_DYN (3 * (G_SA + G_SB))

// ---------------------------------------------------------------------------
// GEMM1 + SwiGLU. 512 thr (16 warps, 4x4). BM=128, BF=128 (x2 matrices).
// ---------------------------------------------------------------------------
__global__ __launch_bounds__(512, 1)
void gemm1_kernel() {
    int e = blockIdx.z;
    int cnt = g_counts[e];
    int base = blockIdx.y * 128;
    if (base >= cnt) return;
    int off = g_offsets[e];
    int f0 = blockIdx.x * 128;

    extern __shared__ char sm[];
    __shared__ int toks[128];
    int tid = threadIdx.x;
    if (tid < 128)
        toks[tid] = (base + tid < cnt) ? g_rowTok[off + base + tid] : -1;
    __syncthreads();

    const __half* W1e = g_W1h + ((size_t)e * FDIM + f0) * DDIM;
    const __half* W2e = g_W2h + ((size_t)e * FDIM + f0) * DDIM;

    int w = tid >> 5, lane = tid & 31;
    int wm = w >> 2, wn = w & 3;
    int g = lane >> 2, tig = lane & 3;

    uint32_t smbase = smem_u32(sm);
    // ldmatrix per-lane address components
    uint32_t arow = (uint32_t)((wm * 32 + (lane & 15)) * RSTRB + (lane >> 4) * 16);
    uint32_t brow = (uint32_t)((wn * 32 + (lane & 7)) * RSTRB + ((lane >> 3) & 1) * 16);

    float acc1[2][4][4], acc2[2][4][4];
    #pragma unroll
    for (int mi = 0; mi < 2; mi++)
        #pragma unroll
        for (int ni = 0; ni < 4; ni++)
            #pragma unroll
            for (int q = 0; q < 4; q++) { acc1[mi][ni][q] = 0.f; acc2[mi][ni][q] = 0.f; }

    const int NKT = DDIM / 32;   // 32

    auto load_stage = [&](int s, int k0) {
        char* smA = sm + s * G_SA;
        char* smB = sm + 3 * G_SA + s * G_SB;
        {
            int row = tid >> 2, q = tid & 3;
            int tok = toks[row];
            const __half* src = g_xh + (size_t)(tok >= 0 ? tok : 0) * DDIM + k0 + q * 8;
            cp16(smA + row * RSTRB + q * 16, src, tok >= 0 ? 16 : 0);
        }
        #pragma unroll
        for (int j = 0; j < 2; j++) {
            int slot = tid + j * 512;
            int r = slot >> 2, q = slot & 3;
            int mat = r >> 7, rw = r & 127;
            const __half* src = (mat ? W2e : W1e) + (size_t)rw * DDIM + k0 + q * 8;
            cp16(smB + r * RSTRB + q * 16, src, 16);
        }
    };

    load_stage(0, 0);  CP_COMMIT();
    load_stage(1, 32); CP_COMMIT();

    for (int kt = 0; kt < NKT; kt++) {
        if (kt + 1 < NKT) CP_WAIT(1); else CP_WAIT(0);
        __syncthreads();
        if (kt + 2 < NKT) { load_stage((kt + 2) % 3, (kt + 2) * 32); CP_COMMIT(); }

        int s = kt % 3;
        uint32_t sa = smbase + s * G_SA;
        uint32_t ub = smbase + 3 * G_SA + s * G_SB;

        #pragma unroll
        for (int ks = 0; ks < 2; ks++) {
            uint32_t a0[4], a1[4];
            ldsm4(a0, sa + arow + ks * 32);
            ldsm4(a1, sa + arow + 16 * RSTRB + ks * 32);
            #pragma unroll
            for (int ni = 0; ni < 4; ni++) {
                uint32_t b1r[2], b2r[2];
                ldsm2(b1r, ub + brow + ni * 8 * RSTRB + ks * 32);
                ldsm2(b2r, ub + brow + (128 + ni * 8) * RSTRB + ks * 32);
                mma_f16(acc1[0][ni], a0, b1r[0], b1r[1]);
                mma_f16(acc1[1][ni], a1, b1r[0], b1r[1]);
                mma_f16(acc2[0][ni], a0, b2r[0], b2r[1]);
                mma_f16(acc2[1][ni], a1, b2r[0], b2r[1]);
            }
        }
    }

    // Epilogue: SwiGLU -> Hh (fp16)
    #pragma unroll
    for (int mi = 0; mi < 2; mi++) {
        int r0 = base + wm * 32 + mi * 16 + g;
        #pragma unroll
        for (int ni = 0; ni < 4; ni++) {
            int col = f0 + wn * 32 + ni * 8 + tig * 2;
            #pragma unroll
            for (int half = 0; half < 2; half++) {
                int row = r0 + half * 8;
                if (row < cnt) {
                    float h1a = acc1[mi][ni][half * 2 + 0];
                    float h1b = acc1[mi][ni][half * 2 + 1];
                    float h2a = acc2[mi][ni][half * 2 + 0];
                    float h2b = acc2[mi][ni][half * 2 + 1];
                    float oa = h1a / (1.f + expf(-h1a)) * h2a;
                    float ob = h1b / (1.f + expf(-h1b)) * h2b;
                    *(__half2*)(g_Hh + (size_t)(off + row) * FDIM + col) =
                        __floats2half2_rn(oa, ob);
                }
            }
        }
    }
}

// ---------------------------------------------------------------------------
// GEMM2: Y = H . W3^T. 512 thr. BM=128, BN=256.
// ---------------------------------------------------------------------------
__global__ __launch_bounds__(512, 1)
void gemm2_kernel() {
    int e = blockIdx.z;
    int cnt = g_counts[e];
    int base = blockIdx.y * 128;
    if (base >= cnt) return;
    int off = g_offsets[e];
    int d0 = blockIdx.x * 256;

    extern __shared__ char sm[];
    int tid = threadIdx.x;

    const __half* W3e = g_W3h + ((size_t)e * DDIM + d0) * FDIM;
    const __half* Ab  = g_Hh + (size_t)(off + base) * FDIM;
    int arows = cnt - base;

    int w = tid >> 5, lane = tid & 31;
    int wm = w >> 2, wn = w & 3;
    int g = lane >> 2, tig = lane & 3;

    uint32_t smbase = smem_u32(sm);
    uint32_t arow = (uint32_t)((wm * 32 + (lane & 15)) * RSTRB + (lane >> 4) * 16);
    uint32_t brow = (uint32_t)((wn * 64 + (lane & 7)) * RSTRB + ((lane >> 3) & 1) * 16);

    float acc[2][8][4];
    #pragma unroll
    for (int mi = 0; mi < 2; mi++)
        #pragma unroll
        for (int ni = 0; ni < 8; ni++)
            #pragma unroll
            for (int q = 0; q < 4; q++) acc[mi][ni][q] = 0.f;

    const int NKT = FDIM / 32;   // 64

    auto load_stage = [&](int s, int k0) {
        char* smA = sm + s * G_SA;
        char* smB = sm + 3 * G_SA + s * G_SB;
        {
            int row = tid >> 2, q = tid & 3;
            const __half* src = Ab + (size_t)(row < arows ? row : 0) * FDIM + k0 + q * 8;
            cp16(smA + row * RSTRB + q * 16, src, row < arows ? 16 : 0);
        }
        #pragma unroll
        for (int j = 0; j < 2; j++) {
            int slot = tid + j * 512;
            int r = slot >> 2, q = slot & 3;
            const __half* src = W3e + (size_t)r * FDIM + k0 + q * 8;
            cp16(smB + r * RSTRB + q * 16, src, 16);
        }
    };

    load_stage(0, 0);  CP_COMMIT();
    load_stage(1, 32); CP_COMMIT();

    for (int kt = 0; kt < NKT; kt++) {
        if (kt + 1 < NKT) CP_WAIT(1); else CP_WAIT(0);
        __syncthreads();
        if (kt + 2 < NKT) { load_stage((kt + 2) % 3, (kt + 2) * 32); CP_COMMIT(); }

        int s = kt % 3;
        uint32_t sa = smbase + s * G_SA;
        uint32_t ub = smbase + 3 * G_SA + s * G_SB;

        #pragma unroll
        for (int ks = 0; ks < 2; ks++) {
            uint32_t a0[4], a1[4];
            ldsm4(a0, sa + arow + ks * 32);
            ldsm4(a1, sa + arow + 16 * RSTRB + ks * 32);
            #pragma unroll
            for (int ni = 0; ni < 8; ni++) {
                uint32_t br[2];
                ldsm2(br, ub + brow + ni * 8 * RSTRB + ks * 32);
                mma_f16(acc[0][ni], a0, br[0], br[1]);
                mma_f16(acc[1][ni], a1, br[0], br[1]);
            }
        }
    }

    #pragma unroll
    for (int mi = 0; mi < 2; mi++) {
        int r0 = base + wm * 32 + mi * 16 + g;
        #pragma unroll
        for (int ni = 0; ni < 8; ni++) {
            int col = d0 + wn * 64 + ni * 8 + tig * 2;
            #pragma unroll
            for (int half = 0; half < 2; half++) {
                int row = r0 + half * 8;
                if (row < cnt) {
                    *(float2*)(g_Y + (size_t)(off + row) * DDIM + col) =
                        make_float2(acc[mi][ni][half * 2 + 0],
                                    acc[mi][ni][half * 2 + 1]);
                }
            }
        }
    }
}

// ---------------------------------------------------------------------------
// Entry point — launch order puts gemm1 at index 3 (the ncu-sampled slot)
// ---------------------------------------------------------------------------
extern "C" void kernel_launch(void* const* d_in, const int* in_sizes, int n_in,
                              void* d_out, int out_size) {
    (void)in_sizes; (void)n_in; (void)out_size;
    const float* x  = (const float*)d_in[0];
    const float* Wg = (const float*)d_in[1];
    const float* W1 = (const float*)d_in[2];
    const float* W2 = (const float*)d_in[3];
    const float* W3 = (const float*)d_in[4];
    float* out = (float*)d_out;

    cudaFuncSetAttribute(gemm1_kernel, cudaFuncAttributeMaxDynamicSharedMemorySize, SMEM_DYN);
    cudaFuncSetAttribute(gemm2_kernel, cudaFuncAttributeMaxDynamicSharedMemorySize, SMEM_DYN);

    convert_kernel<<<CVT_TOTAL / 256, 256>>>(x, W1, W2, W3);        // 0
    gating_kernel<<<TKN, 256>>>(x, Wg);                             // 1
    scatter_kernel<<<TKN / 256, 256>>>();                           // 2
    gemm1_kernel<<<dim3(FDIM / 128, TKN / 128, NEXP), 512, SMEM_DYN>>>();  // 3 (profiled)
    gemm2_kernel<<<dim3(DDIM / 256, TKN / 128, NEXP), 512, SMEM_DYN>>>();  // 4
    combine_kernel<<<TKN, 256>>>(out);                              // 5
}

// round 5
// speedup vs baseline: 2.5439x; 1.1500x over previous
#include <cuda_runtime.h>
#include <cuda_fp16.h>
#include <cstdint>
#include <math.h>

// Problem constants
#define TKN   4096
#define DDIM  1024
#define FDIM  2048
#define NEXP  8
#define NASS  (TKN * 2)

// ---------------------------------------------------------------------------
// Scratch (device globals)
// ---------------------------------------------------------------------------
__device__ int   g_counts[NEXP];
__device__ int   g_offsets[NEXP + 1];
__device__ int   g_cursor[NEXP];
__device__ int   g_rowTok[NASS];
__device__ int   g_assignRow[NASS];
__device__ float g_probs[NASS];
__device__ int   g_topE[NASS];

__device__ __align__(16) __half g_xh[(size_t)TKN * DDIM];
__device__ __align__(16) __half g_W1h[(size_t)NEXP * FDIM * DDIM];
__device__ __align__(16) __half g_W2h[(size_t)NEXP * FDIM * DDIM];
__device__ __align__(16) __half g_W3h[(size_t)NEXP * DDIM * FDIM];
__device__ __align__(16) __half g_Hh[(size_t)NASS * FDIM];
__device__ __align__(16) float  g_Y[(size_t)NASS * DDIM];

// ---------------------------------------------------------------------------
// Helpers
// ---------------------------------------------------------------------------
__device__ __forceinline__ uint32_t smem_u32(const void* p) {
    uint32_t a;
    asm("{ .reg .u64 t; cvta.to.shared.u64 t, %1; cvt.u32.u64 %0, t; }" : "=r"(a) : "l"(p));
    return a;
}
__device__ __forceinline__ void cp16(void* dst, const void* src, int zfill) {
    uint32_t d = smem_u32(dst);
    asm volatile("cp.async.cg.shared.global [%0], [%1], 16, %2;"
                 :: "r"(d), "l"(src), "r"(zfill) : "memory");
}
#define CP_COMMIT() asm volatile("cp.async.commit_group;" ::: "memory")
#define CP_WAIT(n)  asm volatile("cp.async.wait_group %0;" :: "n"(n) : "memory")

__device__ __forceinline__ void mma_f16(float* c, const uint32_t* a,
                                        uint32_t b0, uint32_t b1) {
    asm volatile(
        "mma.sync.aligned.m16n8k16.row.col.f32.f16.f16.f32 "
        "{%0,%1,%2,%3}, {%4,%5,%6,%7}, {%8,%9}, {%0,%1,%2,%3};"
        : "+f"(c[0]), "+f"(c[1]), "+f"(c[2]), "+f"(c[3])
        : "r"(a[0]), "r"(a[1]), "r"(a[2]), "r"(a[3]), "r"(b0), "r"(b1));
}
__device__ __forceinline__ void ldsm4(uint32_t* r, uint32_t a) {
    asm volatile("ldmatrix.sync.aligned.m8n8.x4.shared.b16 {%0,%1,%2,%3}, [%4];"
                 : "=r"(r[0]), "=r"(r[1]), "=r"(r[2]), "=r"(r[3]) : "r"(a));
}
__device__ __forceinline__ void ldsm2(uint32_t* r, uint32_t a) {
    asm volatile("ldmatrix.sync.aligned.m8n8.x2.shared.b16 {%0,%1}, [%2];"
                 : "=r"(r[0]), "=r"(r[1]) : "r"(a));
}

// ---------------------------------------------------------------------------
// Fused fp32->fp16 convert + zero routing counters
// ---------------------------------------------------------------------------
#define X4 (TKN * DDIM / 4)
#define W4 (NEXP * FDIM * DDIM / 4)
#define CVT_TOTAL (X4 + 3 * W4)

__global__ __launch_bounds__(256) void convert_kernel(
    const float* __restrict__ x, const float* __restrict__ W1,
    const float* __restrict__ W2, const float* __restrict__ W3) {
    if (blockIdx.x == 0 && threadIdx.x < NEXP) {
        g_counts[threadIdx.x] = 0;
        g_cursor[threadIdx.x] = 0;
    }
    long i = (long)blockIdx.x * 256 + threadIdx.x;
    const float* s; __half* d; long j;
    if (i < X4)                { s = x;  d = g_xh;  j = i; }
    else if (i < X4 + W4)      { s = W1; d = g_W1h; j = i - X4; }
    else if (i < X4 + 2L * W4) { s = W2; d = g_W2h; j = i - X4 - W4; }
    else if (i < CVT_TOTAL)    { s = W3; d = g_W3h; j = i - X4 - 2L * W4; }
    else return;
    float4 v = ((const float4*)s)[j];
    ((__half2*)d)[2 * j]     = __floats2half2_rn(v.x, v.y);
    ((__half2*)d)[2 * j + 1] = __floats2half2_rn(v.z, v.w);
}

// ---------------------------------------------------------------------------
// Gating
// ---------------------------------------------------------------------------
__global__ __launch_bounds__(256) void gating_kernel(
    const float* __restrict__ x, const float* __restrict__ Wg) {
    int t = blockIdx.x;
    __shared__ float xs[DDIM];
    __shared__ float sc[NEXP];
    for (int i = threadIdx.x; i < DDIM; i += 256)
        xs[i] = x[(size_t)t * DDIM + i];
    __syncthreads();
    int w = threadIdx.x >> 5, lane = threadIdx.x & 31;
    const float* wg = Wg + (size_t)w * DDIM;
    float acc = 0.f;
    #pragma unroll 8
    for (int i = lane; i < DDIM; i += 32) acc += xs[i] * wg[i];
    #pragma unroll
    for (int o = 16; o; o >>= 1) acc += __shfl_xor_sync(0xFFFFFFFFu, acc, o);
    if (lane == 0) sc[w] = acc;
    __syncthreads();
    if (threadIdx.x == 0) {
        int e0 = 0; float s0 = sc[0];
        #pragma unroll
        for (int e = 1; e < NEXP; e++)
            if (sc[e] > s0) { s0 = sc[e]; e0 = e; }
        int e1 = -1; float s1 = -1e30f;
        #pragma unroll
        for (int e = 0; e < NEXP; e++)
            if (e != e0 && sc[e] > s1) { s1 = sc[e]; e1 = e; }
        float z = expf(s1 - s0);
        float inv = 1.f / (1.f + z);
        g_topE[2 * t] = e0;  g_topE[2 * t + 1] = e1;
        g_probs[2 * t] = inv; g_probs[2 * t + 1] = z * inv;
        atomicAdd(&g_counts[e0], 1);
        atomicAdd(&g_counts[e1], 1);
    }
}

// ---------------------------------------------------------------------------
// Scatter (with local scan of the 8 expert counts)
// ---------------------------------------------------------------------------
__global__ __launch_bounds__(256) void scatter_kernel() {
    __shared__ int soff[NEXP];
    if (threadIdx.x < NEXP) {
        int o = 0;
        for (int e = 0; e < threadIdx.x; e++) o += g_counts[e];
        soff[threadIdx.x] = o;
        if (blockIdx.x == 0) {
            g_offsets[threadIdx.x] = o;
            if (threadIdx.x == NEXP - 1) g_offsets[NEXP] = o + g_counts[NEXP - 1];
        }
    }
    __syncthreads();
    int t = blockIdx.x * blockDim.x + threadIdx.x;
    if (t >= TKN) return;
    #pragma unroll
    for (int k = 0; k < 2; k++) {
        int e = g_topE[2 * t + k];
        int pos = soff[e] + atomicAdd(&g_cursor[e], 1);
        g_rowTok[pos] = t;
        g_assignRow[2 * t + k] = pos;
    }
}

__global__ __launch_bounds__(256) void combine_kernel(float* __restrict__ out) {
    int t = blockIdx.x;
    float p0 = g_probs[2 * t], p1 = g_probs[2 * t + 1];
    const float4* y0 = (const float4*)(g_Y + (size_t)g_assignRow[2 * t] * DDIM);
    const float4* y1 = (const float4*)(g_Y + (size_t)g_assignRow[2 * t + 1] * DDIM);
    float4* o = (float4*)(out + (size_t)t * DDIM);
    int i = threadIdx.x;
    float4 a = y0[i], b = y1[i];
    o[i] = make_float4(p0 * a.x + p1 * b.x, p0 * a.y + p1 * b.y,
                       p0 * a.z + p1 * b.z, p0 * a.w + p1 * b.w);
}

// ---------------------------------------------------------------------------
// GEMM tile geometry: 256 threads (8 warps, 4x2), 2 CTAs/SM.
//   K_TILE=32 halves, row stride 40 halves (80 B), 3 stages.
//   A tile 128 rows, B tile 128 rows -> 10240 B each per stage.
// ---------------------------------------------------------------------------
#define RSTRB   80
#define G_SA    (128 * RSTRB)
#define G_SB    (128 * RSTRB)
#define SMEM_DYN (3 * (G_SA + G_SB))   // 61440

// ---------------------------------------------------------------------------
// GEMM1 + SwiGLU. BM=128 rows, BF=64 f-cols (x2 matrices: W1 rows 0-63, W2 64-127).
// Warp (4x2): 32 rows x 32 cols per matrix.
// ---------------------------------------------------------------------------
__global__ __launch_bounds__(256, 2)
void gemm1_kernel() {
    int e = blockIdx.z;
    int cnt = g_counts[e];
    int base = blockIdx.y * 128;
    if (base >= cnt) return;
    int off = g_offsets[e];
    int f0 = blockIdx.x * 64;

    extern __shared__ char sm[];
    __shared__ int toks[128];
    int tid = threadIdx.x;
    if (tid < 128)
        toks[tid] = (base + tid < cnt) ? g_rowTok[off + base + tid] : -1;
    __syncthreads();

    const __half* W1e = g_W1h + ((size_t)e * FDIM + f0) * DDIM;
    const __half* W2e = g_W2h + ((size_t)e * FDIM + f0) * DDIM;

    int w = tid >> 5, lane = tid & 31;
    int wm = w >> 1, wn = w & 1;
    int g = lane >> 2, tig = lane & 3;

    uint32_t smbase = smem_u32(sm);
    uint32_t arow = (uint32_t)((wm * 32 + (lane & 15)) * RSTRB + (lane >> 4) * 16);
    uint32_t brow = (uint32_t)((wn * 32 + (lane & 7)) * RSTRB + ((lane >> 3) & 1) * 16);

    float acc1[2][4][4], acc2[2][4][4];
    #pragma unroll
    for (int mi = 0; mi < 2; mi++)
        #pragma unroll
        for (int ni = 0; ni < 4; ni++)
            #pragma unroll
            for (int q = 0; q < 4; q++) { acc1[mi][ni][q] = 0.f; acc2[mi][ni][q] = 0.f; }

    const int NKT = DDIM / 32;   // 32

    auto load_stage = [&](int s, int k0) {
        char* smA = sm + s * G_SA;
        char* smB = sm + 3 * G_SA + s * G_SB;
        #pragma unroll
        for (int j = 0; j < 2; j++) {   // A: 128 rows x 32h (512 chunks)
            int slot = tid + j * 256;
            int row = slot >> 2, q = slot & 3;
            int tok = toks[row];
            const __half* src = g_xh + (size_t)(tok >= 0 ? tok : 0) * DDIM + k0 + q * 8;
            cp16(smA + row * RSTRB + q * 16, src, tok >= 0 ? 16 : 0);
        }
        #pragma unroll
        for (int j = 0; j < 2; j++) {   // B: 64 W1 rows + 64 W2 rows
            int slot = tid + j * 256;
            int r = slot >> 2, q = slot & 3;
            int mat = r >> 6, rw = r & 63;
            const __half* src = (mat ? W2e : W1e) + (size_t)rw * DDIM + k0 + q * 8;
            cp16(smB + r * RSTRB + q * 16, src, 16);
        }
    };

    load_stage(0, 0);  CP_COMMIT();
    load_stage(1, 32); CP_COMMIT();

    for (int kt = 0; kt < NKT; kt++) {
        if (kt + 1 < NKT) CP_WAIT(1); else CP_WAIT(0);
        __syncthreads();
        if (kt + 2 < NKT) { load_stage((kt + 2) % 3, (kt + 2) * 32); CP_COMMIT(); }

        int s = kt % 3;
        uint32_t sa = smbase + s * G_SA;
        uint32_t ub = smbase + 3 * G_SA + s * G_SB;

        #pragma unroll
        for (int ks = 0; ks < 2; ks++) {
            uint32_t a0[4], a1[4];
            ldsm4(a0, sa + arow + ks * 32);
            ldsm4(a1, sa + arow + 16 * RSTRB + ks * 32);
            #pragma unroll
            for (int ni = 0; ni < 4; ni++) {
                uint32_t b1r[2], b2r[2];
                ldsm2(b1r, ub + brow + ni * 8 * RSTRB + ks * 32);
                ldsm2(b2r, ub + brow + (64 + ni * 8) * RSTRB + ks * 32);
                mma_f16(acc1[0][ni], a0, b1r[0], b1r[1]);
                mma_f16(acc1[1][ni], a1, b1r[0], b1r[1]);
                mma_f16(acc2[0][ni], a0, b2r[0], b2r[1]);
                mma_f16(acc2[1][ni], a1, b2r[0], b2r[1]);
            }
        }
    }

    // Epilogue: SwiGLU -> Hh (fp16)
    #pragma unroll
    for (int mi = 0; mi < 2; mi++) {
        int r0 = base + wm * 32 + mi * 16 + g;
        #pragma unroll
        for (int ni = 0; ni < 4; ni++) {
            int col = f0 + wn * 32 + ni * 8 + tig * 2;
            #pragma unroll
            for (int half = 0; half < 2; half++) {
                int row = r0 + half * 8;
                if (row < cnt) {
                    float h1a = acc1[mi][ni][half * 2 + 0];
                    float h1b = acc1[mi][ni][half * 2 + 1];
                    float h2a = acc2[mi][ni][half * 2 + 0];
                    float h2b = acc2[mi][ni][half * 2 + 1];
                    float oa = h1a / (1.f + expf(-h1a)) * h2a;
                    float ob = h1b / (1.f + expf(-h1b)) * h2b;
                    *(__half2*)(g_Hh + (size_t)(off + row) * FDIM + col) =
                        __floats2half2_rn(oa, ob);
                }
            }
        }
    }
}

// ---------------------------------------------------------------------------
// GEMM2: Y = H . W3^T. BM=128 rows, BN=128 d-cols. Warp (4x2): 32 x 64.
// ---------------------------------------------------------------------------
__global__ __launch_bounds__(256, 2)
void gemm2_kernel() {
    int e = blockIdx.z;
    int cnt = g_counts[e];
    int base = blockIdx.y * 128;
    if (base >= cnt) return;
    int off = g_offsets[e];
    int d0 = blockIdx.x * 128;

    extern __shared__ char sm[];
    int tid = threadIdx.x;

    const __half* W3e = g_W3h + ((size_t)e * DDIM + d0) * FDIM;
    const __half* Ab  = g_Hh + (size_t)(off + base) * FDIM;
    int arows = cnt - base;

    int w = tid >> 5, lane = tid & 31;
    int wm = w >> 1, wn = w & 1;
    int g = lane >> 2, tig = lane & 3;

    uint32_t smbase = smem_u32(sm);
    uint32_t arow = (uint32_t)((wm * 32 + (lane & 15)) * RSTRB + (lane >> 4) * 16);
    uint32_t brow = (uint32_t)((wn * 64 + (lane & 7)) * RSTRB + ((lane >> 3) & 1) * 16);

    float acc[2][8][4];
    #pragma unroll
    for (int mi = 0; mi < 2; mi++)
        #pragma unroll
        for (int ni = 0; ni < 8; ni++)
            #pragma unroll
            for (int q = 0; q < 4; q++) acc[mi][ni][q] = 0.f;

    const int NKT = FDIM / 32;   // 64

    auto load_stage = [&](int s, int k0) {
        char* smA = sm + s * G_SA;
        char* smB = sm + 3 * G_SA + s * G_SB;
        #pragma unroll
        for (int j = 0; j < 2; j++) {
            int slot = tid + j * 256;
            int row = slot >> 2, q = slot & 3;
            const __half* src = Ab + (size_t)(row < arows ? row : 0) * FDIM + k0 + q * 8;
            cp16(smA + row * RSTRB + q * 16, src, row < arows ? 16 : 0);
        }
        #pragma unroll
        for (int j = 0; j < 2; j++) {
            int slot = tid + j * 256;
            int r = slot >> 2, q = slot & 3;
            const __half* src = W3e + (size_t)r * FDIM + k0 + q * 8;
            cp16(smB + r * RSTRB + q * 16, src, 16);
        }
    };

    load_stage(0, 0);  CP_COMMIT();
    load_stage(1, 32); CP_COMMIT();

    for (int kt = 0; kt < NKT; kt++) {
        if (kt + 1 < NKT) CP_WAIT(1); else CP_WAIT(0);
        __syncthreads();
        if (kt + 2 < NKT) { load_stage((kt + 2) % 3, (kt + 2) * 32); CP_COMMIT(); }

        int s = kt % 3;
        uint32_t sa = smbase + s * G_SA;
        uint32_t ub = smbase + 3 * G_SA + s * G_SB;

        #pragma unroll
        for (int ks = 0; ks < 2; ks++) {
            uint32_t a0[4], a1[4];
            ldsm4(a0, sa + arow + ks * 32);
            ldsm4(a1, sa + arow + 16 * RSTRB + ks * 32);
            #pragma unroll
            for (int ni = 0; ni < 8; ni++) {
                uint32_t br[2];
                ldsm2(br, ub + brow + ni * 8 * RSTRB + ks * 32);
                mma_f16(acc[0][ni], a0, br[0], br[1]);
                mma_f16(acc[1][ni], a1, br[0], br[1]);
            }
        }
    }

    #pragma unroll
    for (int mi = 0; mi < 2; mi++) {
        int r0 = base + wm * 32 + mi * 16 + g;
        #pragma unroll
        for (int ni = 0; ni < 8; ni++) {
            int col = d0 + wn * 64 + ni * 8 + tig * 2;
            #pragma unroll
            for (int half = 0; half < 2; half++) {
                int row = r0 + half * 8;
                if (row < cnt) {
                    *(float2*)(g_Y + (size_t)(off + row) * DDIM + col) =
                        make_float2(acc[mi][ni][half * 2 + 0],
                                    acc[mi][ni][half * 2 + 1]);
                }
            }
        }
    }
}

// ---------------------------------------------------------------------------
// Entry point — gemm1 stays at launch index 3 (the ncu-sampled slot)
// ---------------------------------------------------------------------------
extern "C" void kernel_launch(void* const* d_in, const int* in_sizes, int n_in,
                              void* d_out, int out_size) {
    (void)in_sizes; (void)n_in; (void)out_size;
    const float* x  = (const float*)d_in[0];
    const float* Wg = (const float*)d_in[1];
    const float* W1 = (const float*)d_in[2];
    const float* W2 = (const float*)d_in[3];
    const float* W3 = (const float*)d_in[4];
    float* out = (float*)d_out;

    cudaFuncSetAttribute(gemm1_kernel, cudaFuncAttributeMaxDynamicSharedMemorySize, SMEM_DYN);
    cudaFuncSetAttribute(gemm2_kernel, cudaFuncAttributeMaxDynamicSharedMemorySize, SMEM_DYN);

    convert_kernel<<<CVT_TOTAL / 256, 256>>>(x, W1, W2, W3);        // 0
    gating_kernel<<<TKN, 256>>>(x, Wg);                             // 1
    scatter_kernel<<<TKN / 256, 256>>>();                           // 2
    gemm1_kernel<<<dim3(FDIM / 64, TKN / 128, NEXP), 256, SMEM_DYN>>>();   // 3 (profiled)
    gemm2_kernel<<<dim3(DDIM / 128, TKN / 128, NEXP), 256, SMEM_DYN>>>();  // 4
    combine_kernel<<<TKN, 256>>>(out);                              // 5
}

// round 6
// speedup vs baseline: 2.7862x; 1.0953x over previous
#include <cuda_runtime.h>
#include <cuda_fp16.h>
#include <cstdint>
#include <math.h>

// Problem constants
#define TKN   4096
#define DDIM  1024
#define FDIM  2048
#define NEXP  8
#define NASS  (TKN * 2)

// ---------------------------------------------------------------------------
// Scratch (device globals)
// ---------------------------------------------------------------------------
__device__ int   g_counts[NEXP];
__device__ int   g_offsets[NEXP + 1];
__device__ int   g_cursor[NEXP];
__device__ int   g_rowTok[NASS];
__device__ int   g_assignRow[NASS];
__device__ float g_probs[NASS];
__device__ int   g_topE[NASS];

__device__ __align__(16) __half g_xh[(size_t)TKN * DDIM];
__device__ __align__(16) __half g_W1h[(size_t)NEXP * FDIM * DDIM];
__device__ __align__(16) __half g_W2h[(size_t)NEXP * FDIM * DDIM];
__device__ __align__(16) __half g_W3h[(size_t)NEXP * DDIM * FDIM];
__device__ __align__(16) __half g_Hh[(size_t)NASS * FDIM];
__device__ __align__(16) float  g_Y[(size_t)NASS * DDIM];

// ---------------------------------------------------------------------------
// Helpers
// ---------------------------------------------------------------------------
__device__ __forceinline__ uint32_t smem_u32(const void* p) {
    uint32_t a;
    asm("{ .reg .u64 t; cvta.to.shared.u64 t, %1; cvt.u32.u64 %0, t; }" : "=r"(a) : "l"(p));
    return a;
}
__device__ __forceinline__ void cp16(void* dst, const void* src, int zfill) {
    uint32_t d = smem_u32(dst);
    asm volatile("cp.async.cg.shared.global [%0], [%1], 16, %2;"
                 :: "r"(d), "l"(src), "r"(zfill) : "memory");
}
#define CP_COMMIT() asm volatile("cp.async.commit_group;" ::: "memory")
#define CP_WAIT(n)  asm volatile("cp.async.wait_group %0;" :: "n"(n) : "memory")

__device__ __forceinline__ void mma_f16(float* c, const uint32_t* a,
                                        uint32_t b0, uint32_t b1) {
    asm volatile(
        "mma.sync.aligned.m16n8k16.row.col.f32.f16.f16.f32 "
        "{%0,%1,%2,%3}, {%4,%5,%6,%7}, {%8,%9}, {%0,%1,%2,%3};"
        : "+f"(c[0]), "+f"(c[1]), "+f"(c[2]), "+f"(c[3])
        : "r"(a[0]), "r"(a[1]), "r"(a[2]), "r"(a[3]), "r"(b0), "r"(b1));
}
__device__ __forceinline__ void ldsm4(uint32_t* r, uint32_t a) {
    asm volatile("ldmatrix.sync.aligned.m8n8.x4.shared.b16 {%0,%1,%2,%3}, [%4];"
                 : "=r"(r[0]), "=r"(r[1]), "=r"(r[2]), "=r"(r[3]) : "r"(a));
}
__device__ __forceinline__ void ldsm2(uint32_t* r, uint32_t a) {
    asm volatile("ldmatrix.sync.aligned.m8n8.x2.shared.b16 {%0,%1}, [%2];"
                 : "=r"(r[0]), "=r"(r[1]) : "r"(a));
}

// ---------------------------------------------------------------------------
// Fused fp32->fp16 convert + zero routing counters
// ---------------------------------------------------------------------------
#define X4 (TKN * DDIM / 4)
#define W4 (NEXP * FDIM * DDIM / 4)
#define CVT_TOTAL (X4 + 3 * W4)

__global__ __launch_bounds__(256) void convert_kernel(
    const float* __restrict__ x, const float* __restrict__ W1,
    const float* __restrict__ W2, const float* __restrict__ W3) {
    if (blockIdx.x == 0 && threadIdx.x < NEXP) {
        g_counts[threadIdx.x] = 0;
        g_cursor[threadIdx.x] = 0;
    }
    long i = (long)blockIdx.x * 256 + threadIdx.x;
    const float* s; __half* d; long j;
    if (i < X4)                { s = x;  d = g_xh;  j = i; }
    else if (i < X4 + W4)      { s = W1; d = g_W1h; j = i - X4; }
    else if (i < X4 + 2L * W4) { s = W2; d = g_W2h; j = i - X4 - W4; }
    else if (i < CVT_TOTAL)    { s = W3; d = g_W3h; j = i - X4 - 2L * W4; }
    else return;
    float4 v = ((const float4*)s)[j];
    ((__half2*)d)[2 * j]     = __floats2half2_rn(v.x, v.y);
    ((__half2*)d)[2 * j + 1] = __floats2half2_rn(v.z, v.w);
}

// ---------------------------------------------------------------------------
// Gating
// ---------------------------------------------------------------------------
__global__ __launch_bounds__(256) void gating_kernel(
    const float* __restrict__ x, const float* __restrict__ Wg) {
    int t = blockIdx.x;
    __shared__ float xs[DDIM];
    __shared__ float sc[NEXP];
    for (int i = threadIdx.x; i < DDIM; i += 256)
        xs[i] = x[(size_t)t * DDIM + i];
    __syncthreads();
    int w = threadIdx.x >> 5, lane = threadIdx.x & 31;
    const float* wg = Wg + (size_t)w * DDIM;
    float acc = 0.f;
    #pragma unroll 8
    for (int i = lane; i < DDIM; i += 32) acc += xs[i] * wg[i];
    #pragma unroll
    for (int o = 16; o; o >>= 1) acc += __shfl_xor_sync(0xFFFFFFFFu, acc, o);
    if (lane == 0) sc[w] = acc;
    __syncthreads();
    if (threadIdx.x == 0) {
        int e0 = 0; float s0 = sc[0];
        #pragma unroll
        for (int e = 1; e < NEXP; e++)
            if (sc[e] > s0) { s0 = sc[e]; e0 = e; }
        int e1 = -1; float s1 = -1e30f;
        #pragma unroll
        for (int e = 0; e < NEXP; e++)
            if (e != e0 && sc[e] > s1) { s1 = sc[e]; e1 = e; }
        float z = expf(s1 - s0);
        float inv = 1.f / (1.f + z);
        g_topE[2 * t] = e0;  g_topE[2 * t + 1] = e1;
        g_probs[2 * t] = inv; g_probs[2 * t + 1] = z * inv;
        atomicAdd(&g_counts[e0], 1);
        atomicAdd(&g_counts[e1], 1);
    }
}

// ---------------------------------------------------------------------------
// Scatter (with local scan of the 8 expert counts)
// ---------------------------------------------------------------------------
__global__ __launch_bounds__(256) void scatter_kernel() {
    __shared__ int soff[NEXP];
    if (threadIdx.x < NEXP) {
        int o = 0;
        for (int e = 0; e < threadIdx.x; e++) o += g_counts[e];
        soff[threadIdx.x] = o;
        if (blockIdx.x == 0) {
            g_offsets[threadIdx.x] = o;
            if (threadIdx.x == NEXP - 1) g_offsets[NEXP] = o + g_counts[NEXP - 1];
        }
    }
    __syncthreads();
    int t = blockIdx.x * blockDim.x + threadIdx.x;
    if (t >= TKN) return;
    #pragma unroll
    for (int k = 0; k < 2; k++) {
        int e = g_topE[2 * t + k];
        int pos = soff[e] + atomicAdd(&g_cursor[e], 1);
        g_rowTok[pos] = t;
        g_assignRow[2 * t + k] = pos;
    }
}

__global__ __launch_bounds__(256) void combine_kernel(float* __restrict__ out) {
    int t = blockIdx.x;
    float p0 = g_probs[2 * t], p1 = g_probs[2 * t + 1];
    const float4* y0 = (const float4*)(g_Y + (size_t)g_assignRow[2 * t] * DDIM);
    const float4* y1 = (const float4*)(g_Y + (size_t)g_assignRow[2 * t + 1] * DDIM);
    float4* o = (float4*)(out + (size_t)t * DDIM);
    int i = threadIdx.x;
    float4 a = y0[i], b = y1[i];
    o[i] = make_float4(p0 * a.x + p1 * b.x, p0 * a.y + p1 * b.y,
                       p0 * a.z + p1 * b.z, p0 * a.w + p1 * b.w);
}

// ---------------------------------------------------------------------------
// GEMM tile geometry: 256 threads (8 warps, 4x2), 2 CTAs/SM.
//   K_TILE = 64 halves (128 B + 16 pad -> 144 B row stride), 3 stages.
//   A tile 128 rows, B tile 128 rows -> 18432 B each per stage.
// ---------------------------------------------------------------------------
#define KT      64
#define RSTRB   144
#define G_SA    (128 * RSTRB)
#define STAGE   (2 * G_SA)             // 36864
#define SMEM_DYN (3 * STAGE)           // 110592

// ---------------------------------------------------------------------------
// GEMM1 + SwiGLU. BM=128 rows, BF=64 f-cols (x2 matrices: W1 rows 0-63, W2 64-127).
// Warp (4x2): 32 rows x 32 cols per matrix. Batched fragment loads per k-step.
// ---------------------------------------------------------------------------
__global__ __launch_bounds__(256, 2)
void gemm1_kernel() {
    int e = blockIdx.z;
    int cnt = g_counts[e];
    int base = blockIdx.y * 128;
    if (base >= cnt) return;
    int off = g_offsets[e];
    int f0 = blockIdx.x * 64;

    extern __shared__ char sm[];
    __shared__ int toks[128];
    int tid = threadIdx.x;
    if (tid < 128)
        toks[tid] = (base + tid < cnt) ? g_rowTok[off + base + tid] : -1;
    __syncthreads();

    const __half* W1e = g_W1h + ((size_t)e * FDIM + f0) * DDIM;
    const __half* W2e = g_W2h + ((size_t)e * FDIM + f0) * DDIM;

    int w = tid >> 5, lane = tid & 31;
    int wm = w >> 1, wn = w & 1;
    int g = lane >> 2, tig = lane & 3;

    uint32_t smbase = smem_u32(sm);
    uint32_t arow = (uint32_t)((wm * 32 + (lane & 15)) * RSTRB + (lane >> 4) * 16);
    uint32_t brow = (uint32_t)((wn * 32 + (lane & 7)) * RSTRB + ((lane >> 3) & 1) * 16);

    float acc1[2][4][4], acc2[2][4][4];
    #pragma unroll
    for (int mi = 0; mi < 2; mi++)
        #pragma unroll
        for (int ni = 0; ni < 4; ni++)
            #pragma unroll
            for (int q = 0; q < 4; q++) { acc1[mi][ni][q] = 0.f; acc2[mi][ni][q] = 0.f; }

    const int NKT = DDIM / KT;   // 16

    auto load_stage = [&](int s, int k0) {
        char* smA = sm + s * STAGE;
        char* smB = smA + G_SA;
        #pragma unroll
        for (int j = 0; j < 4; j++) {   // A: 128 rows x 8 chunks
            int slot = tid + j * 256;
            int row = slot >> 3, q = slot & 7;
            int tok = toks[row];
            const __half* src = g_xh + (size_t)(tok >= 0 ? tok : 0) * DDIM + k0 + q * 8;
            cp16(smA + row * RSTRB + q * 16, src, tok >= 0 ? 16 : 0);
        }
        #pragma unroll
        for (int j = 0; j < 4; j++) {   // B: 64 W1 rows + 64 W2 rows
            int slot = tid + j * 256;
            int r = slot >> 3, q = slot & 7;
            int mat = r >> 6, rw = r & 63;
            const __half* src = (mat ? W2e : W1e) + (size_t)rw * DDIM + k0 + q * 8;
            cp16(smB + r * RSTRB + q * 16, src, 16);
        }
    };

    load_stage(0, 0);  CP_COMMIT();
    load_stage(1, KT); CP_COMMIT();

    for (int kt = 0; kt < NKT; kt++) {
        if (kt + 1 < NKT) CP_WAIT(1); else CP_WAIT(0);
        __syncthreads();
        if (kt + 2 < NKT) { load_stage((kt + 2) % 3, (kt + 2) * KT); CP_COMMIT(); }

        int s = kt % 3;
        uint32_t sa = smbase + s * STAGE;
        uint32_t ub = sa + G_SA;

        #pragma unroll
        for (int ks = 0; ks < 4; ks++) {
            // --- batched fragment loads (10 ldmatrix, no interleaved MMA) ---
            uint32_t a0[4], a1[4], b1f[4][2], b2f[4][2];
            ldsm4(a0, sa + arow + ks * 32);
            ldsm4(a1, sa + arow + 16 * RSTRB + ks * 32);
            #pragma unroll
            for (int ni = 0; ni < 4; ni++)
                ldsm2(b1f[ni], ub + brow + ni * 8 * RSTRB + ks * 32);
            #pragma unroll
            for (int ni = 0; ni < 4; ni++)
                ldsm2(b2f[ni], ub + brow + (64 + ni * 8) * RSTRB + ks * 32);
            // --- 16 back-to-back MMAs ---
            #pragma unroll
            for (int ni = 0; ni < 4; ni++) {
                mma_f16(acc1[0][ni], a0, b1f[ni][0], b1f[ni][1]);
                mma_f16(acc1[1][ni], a1, b1f[ni][0], b1f[ni][1]);
                mma_f16(acc2[0][ni], a0, b2f[ni][0], b2f[ni][1]);
                mma_f16(acc2[1][ni], a1, b2f[ni][0], b2f[ni][1]);
            }
        }
    }

    // Epilogue: SwiGLU -> Hh (fp16)
    #pragma unroll
    for (int mi = 0; mi < 2; mi++) {
        int r0 = base + wm * 32 + mi * 16 + g;
        #pragma unroll
        for (int ni = 0; ni < 4; ni++) {
            int col = f0 + wn * 32 + ni * 8 + tig * 2;
            #pragma unroll
            for (int half = 0; half < 2; half++) {
                int row = r0 + half * 8;
                if (row < cnt) {
                    float h1a = acc1[mi][ni][half * 2 + 0];
                    float h1b = acc1[mi][ni][half * 2 + 1];
                    float h2a = acc2[mi][ni][half * 2 + 0];
                    float h2b = acc2[mi][ni][half * 2 + 1];
                    float oa = h1a / (1.f + expf(-h1a)) * h2a;
                    float ob = h1b / (1.f + expf(-h1b)) * h2b;
                    *(__half2*)(g_Hh + (size_t)(off + row) * FDIM + col) =
                        __floats2half2_rn(oa, ob);
                }
            }
        }
    }
}

// ---------------------------------------------------------------------------
// GEMM2: Y = H . W3^T. BM=128 rows, BN=128 d-cols. Warp (4x2): 32 x 64.
// ---------------------------------------------------------------------------
__global__ __launch_bounds__(256, 2)
void gemm2_kernel() {
    int e = blockIdx.z;
    int cnt = g_counts[e];
    int base = blockIdx.y * 128;
    if (base >= cnt) return;
    int off = g_offsets[e];
    int d0 = blockIdx.x * 128;

    extern __shared__ char sm[];
    int tid = threadIdx.x;

    const __half* W3e = g_W3h + ((size_t)e * DDIM + d0) * FDIM;
    const __half* Ab  = g_Hh + (size_t)(off + base) * FDIM;
    int arows = cnt - base;

    int w = tid >> 5, lane = tid & 31;
    int wm = w >> 1, wn = w & 1;
    int g = lane >> 2, tig = lane & 3;

    uint32_t smbase = smem_u32(sm);
    uint32_t arow = (uint32_t)((wm * 32 + (lane & 15)) * RSTRB + (lane >> 4) * 16);
    uint32_t brow = (uint32_t)((wn * 64 + (lane & 7)) * RSTRB + ((lane >> 3) & 1) * 16);

    float acc[2][8][4];
    #pragma unroll
    for (int mi = 0; mi < 2; mi++)
        #pragma unroll
        for (int ni = 0; ni < 8; ni++)
            #pragma unroll
            for (int q = 0; q < 4; q++) acc[mi][ni][q] = 0.f;

    const int NKT = FDIM / KT;   // 32

    auto load_stage = [&](int s, int k0) {
        char* smA = sm + s * STAGE;
        char* smB = smA + G_SA;
        #pragma unroll
        for (int j = 0; j < 4; j++) {
            int slot = tid + j * 256;
            int row = slot >> 3, q = slot & 7;
            const __half* src = Ab + (size_t)(row < arows ? row : 0) * FDIM + k0 + q * 8;
            cp16(smA + row * RSTRB + q * 16, src, row < arows ? 16 : 0);
        }
        #pragma unroll
        for (int j = 0; j < 4; j++) {
            int slot = tid + j * 256;
            int r = slot >> 3, q = slot & 7;
            const __half* src = W3e + (size_t)r * FDIM + k0 + q * 8;
            cp16(smB + r * RSTRB + q * 16, src, 16);
        }
    };

    load_stage(0, 0);  CP_COMMIT();
    load_stage(1, KT); CP_COMMIT();

    for (int kt = 0; kt < NKT; kt++) {
        if (kt + 1 < NKT) CP_WAIT(1); else CP_WAIT(0);
        __syncthreads();
        if (kt + 2 < NKT) { load_stage((kt + 2) % 3, (kt + 2) * KT); CP_COMMIT(); }

        int s = kt % 3;
        uint32_t sa = smbase + s * STAGE;
        uint32_t ub = sa + G_SA;

        #pragma unroll
        for (int ks = 0; ks < 4; ks++) {
            uint32_t a0[4], a1[4], bf[8][2];
            ldsm4(a0, sa + arow + ks * 32);
            ldsm4(a1, sa + arow + 16 * RSTRB + ks * 32);
            #pragma unroll
            for (int ni = 0; ni < 8; ni++)
                ldsm2(bf[ni], ub + brow + ni * 8 * RSTRB + ks * 32);
            #pragma unroll
            for (int ni = 0; ni < 8; ni++) {
                mma_f16(acc[0][ni], a0, bf[ni][0], bf[ni][1]);
                mma_f16(acc[1][ni], a1, bf[ni][0], bf[ni][1]);
            }
        }
    }

    #pragma unroll
    for (int mi = 0; mi < 2; mi++) {
        int r0 = base + wm * 32 + mi * 16 + g;
        #pragma unroll
        for (int ni = 0; ni < 8; ni++) {
            int col = d0 + wn * 64 + ni * 8 + tig * 2;
            #pragma unroll
            for (int half = 0; half < 2; half++) {
                int row = r0 + half * 8;
                if (row < cnt) {
                    *(float2*)(g_Y + (size_t)(off + row) * DDIM + col) =
                        make_float2(acc[mi][ni][half * 2 + 0],
                                    acc[mi][ni][half * 2 + 1]);
                }
            }
        }
    }
}

// ---------------------------------------------------------------------------
// Entry point — gemm1 stays at launch index 3 (the ncu-sampled slot)
// ---------------------------------------------------------------------------
extern "C" void kernel_launch(void* const* d_in, const int* in_sizes, int n_in,
                              void* d_out, int out_size) {
    (void)in_sizes; (void)n_in; (void)out_size;
    const float* x  = (const float*)d_in[0];
    const float* Wg = (const float*)d_in[1];
    const float* W1 = (const float*)d_in[2];
    const float* W2 = (const float*)d_in[3];
    const float* W3 = (const float*)d_in[4];
    float* out = (float*)d_out;

    cudaFuncSetAttribute(gemm1_kernel, cudaFuncAttributeMaxDynamicSharedMemorySize, SMEM_DYN);
    cudaFuncSetAttribute(gemm2_kernel, cudaFuncAttributeMaxDynamicSharedMemorySize, SMEM_DYN);

    convert_kernel<<<CVT_TOTAL / 256, 256>>>(x, W1, W2, W3);        // 0
    gating_kernel<<<TKN, 256>>>(x, Wg);                             // 1
    scatter_kernel<<<TKN / 256, 256>>>();                           // 2
    gemm1_kernel<<<dim3(FDIM / 64, TKN / 128, NEXP), 256, SMEM_DYN>>>();   // 3 (profiled)
    gemm2_kernel<<<dim3(DDIM / 128, TKN / 128, NEXP), 256, SMEM_DYN>>>();  // 4
    combine_kernel<<<TKN, 256>>>(out);                              // 5
}

// round 7
// speedup vs baseline: 2.8876x; 1.0364x over previous
#include <cuda_runtime.h>
#include <cuda_fp16.h>
#include <cstdint>
#include <math.h>

// Problem constants
#define TKN   4096
#define DDIM  1024
#define FDIM  2048
#define NEXP  8
#define NASS  (TKN * 2)

// ---------------------------------------------------------------------------
// Scratch (device globals)
// ---------------------------------------------------------------------------
__device__ int   g_counts[NEXP];
__device__ int   g_offsets[NEXP + 1];
__device__ int   g_cursor[NEXP];
__device__ int   g_rowTok[NASS];
__device__ int   g_assignRow[NASS];
__device__ float g_probs[NASS];
__device__ int   g_topE[NASS];

__device__ __align__(16) __half g_xh[(size_t)TKN * DDIM];
__device__ __align__(16) __half g_W1h[(size_t)NEXP * FDIM * DDIM];
__device__ __align__(16) __half g_W2h[(size_t)NEXP * FDIM * DDIM];
__device__ __align__(16) __half g_W3h[(size_t)NEXP * DDIM * FDIM];
__device__ __align__(16) __half g_Hh[(size_t)NASS * FDIM];
__device__ __align__(16) float  g_Y[(size_t)NASS * DDIM];

// ---------------------------------------------------------------------------
// Helpers
// ---------------------------------------------------------------------------
__device__ __forceinline__ uint32_t smem_u32(const void* p) {
    uint32_t a;
    asm("{ .reg .u64 t; cvta.to.shared.u64 t, %1; cvt.u32.u64 %0, t; }" : "=r"(a) : "l"(p));
    return a;
}
__device__ __forceinline__ void cp16(void* dst, const void* src, int zfill) {
    uint32_t d = smem_u32(dst);
    asm volatile("cp.async.cg.shared.global [%0], [%1], 16, %2;"
                 :: "r"(d), "l"(src), "r"(zfill) : "memory");
}
#define CP_COMMIT() asm volatile("cp.async.commit_group;" ::: "memory")
#define CP_WAIT(n)  asm volatile("cp.async.wait_group %0;" :: "n"(n) : "memory")

__device__ __forceinline__ void mma_f16(float* c, const uint32_t* a,
                                        uint32_t b0, uint32_t b1) {
    asm volatile(
        "mma.sync.aligned.m16n8k16.row.col.f32.f16.f16.f32 "
        "{%0,%1,%2,%3}, {%4,%5,%6,%7}, {%8,%9}, {%0,%1,%2,%3};"
        : "+f"(c[0]), "+f"(c[1]), "+f"(c[2]), "+f"(c[3])
        : "r"(a[0]), "r"(a[1]), "r"(a[2]), "r"(a[3]), "r"(b0), "r"(b1));
}
__device__ __forceinline__ void ldsm4(uint32_t* r, uint32_t a) {
    asm volatile("ldmatrix.sync.aligned.m8n8.x4.shared.b16 {%0,%1,%2,%3}, [%4];"
                 : "=r"(r[0]), "=r"(r[1]), "=r"(r[2]), "=r"(r[3]) : "r"(a));
}

// ---------------------------------------------------------------------------
// Fused fp32->fp16 convert + zero routing counters
// ---------------------------------------------------------------------------
#define X4 (TKN * DDIM / 4)
#define W4 (NEXP * FDIM * DDIM / 4)
#define CVT_TOTAL (X4 + 3 * W4)

__global__ __launch_bounds__(256) void convert_kernel(
    const float* __restrict__ x, const float* __restrict__ W1,
    const float* __restrict__ W2, const float* __restrict__ W3) {
    if (blockIdx.x == 0 && threadIdx.x < NEXP) {
        g_counts[threadIdx.x] = 0;
        g_cursor[threadIdx.x] = 0;
    }
    long i = (long)blockIdx.x * 256 + threadIdx.x;
    const float* s; __half* d; long j;
    if (i < X4)                { s = x;  d = g_xh;  j = i; }
    else if (i < X4 + W4)      { s = W1; d = g_W1h; j = i - X4; }
    else if (i < X4 + 2L * W4) { s = W2; d = g_W2h; j = i - X4 - W4; }
    else if (i < CVT_TOTAL)    { s = W3; d = g_W3h; j = i - X4 - 2L * W4; }
    else return;
    float4 v = ((const float4*)s)[j];
    ((__half2*)d)[2 * j]     = __floats2half2_rn(v.x, v.y);
    ((__half2*)d)[2 * j + 1] = __floats2half2_rn(v.z, v.w);
}

// ---------------------------------------------------------------------------
// Gating
// ---------------------------------------------------------------------------
__global__ __launch_bounds__(256) void gating_kernel(
    const float* __restrict__ x, const float* __restrict__ Wg) {
    int t = blockIdx.x;
    __shared__ float xs[DDIM];
    __shared__ float sc[NEXP];
    for (int i = threadIdx.x; i < DDIM; i += 256)
        xs[i] = x[(size_t)t * DDIM + i];
    __syncthreads();
    int w = threadIdx.x >> 5, lane = threadIdx.x & 31;
    const float* wg = Wg + (size_t)w * DDIM;
    float acc = 0.f;
    #pragma unroll 8
    for (int i = lane; i < DDIM; i += 32) acc += xs[i] * wg[i];
    #pragma unroll
    for (int o = 16; o; o >>= 1) acc += __shfl_xor_sync(0xFFFFFFFFu, acc, o);
    if (lane == 0) sc[w] = acc;
    __syncthreads();
    if (threadIdx.x == 0) {
        int e0 = 0; float s0 = sc[0];
        #pragma unroll
        for (int e = 1; e < NEXP; e++)
            if (sc[e] > s0) { s0 = sc[e]; e0 = e; }
        int e1 = -1; float s1 = -1e30f;
        #pragma unroll
        for (int e = 0; e < NEXP; e++)
            if (e != e0 && sc[e] > s1) { s1 = sc[e]; e1 = e; }
        float z = expf(s1 - s0);
        float inv = 1.f / (1.f + z);
        g_topE[2 * t] = e0;  g_topE[2 * t + 1] = e1;
        g_probs[2 * t] = inv; g_probs[2 * t + 1] = z * inv;
        atomicAdd(&g_counts[e0], 1);
        atomicAdd(&g_counts[e1], 1);
    }
}

// ---------------------------------------------------------------------------
// Scatter (with local scan of the 8 expert counts)
// ---------------------------------------------------------------------------
__global__ __launch_bounds__(256) void scatter_kernel() {
    __shared__ int soff[NEXP];
    if (threadIdx.x < NEXP) {
        int o = 0;
        for (int e = 0; e < threadIdx.x; e++) o += g_counts[e];
        soff[threadIdx.x] = o;
        if (blockIdx.x == 0) {
            g_offsets[threadIdx.x] = o;
            if (threadIdx.x == NEXP - 1) g_offsets[NEXP] = o + g_counts[NEXP - 1];
        }
    }
    __syncthreads();
    int t = blockIdx.x * blockDim.x + threadIdx.x;
    if (t >= TKN) return;
    #pragma unroll
    for (int k = 0; k < 2; k++) {
        int e = g_topE[2 * t + k];
        int pos = soff[e] + atomicAdd(&g_cursor[e], 1);
        g_rowTok[pos] = t;
        g_assignRow[2 * t + k] = pos;
    }
}

__global__ __launch_bounds__(256) void combine_kernel(float* __restrict__ out) {
    int t = blockIdx.x;
    float p0 = g_probs[2 * t], p1 = g_probs[2 * t + 1];
    const float4* y0 = (const float4*)(g_Y + (size_t)g_assignRow[2 * t] * DDIM);
    const float4* y1 = (const float4*)(g_Y + (size_t)g_assignRow[2 * t + 1] * DDIM);
    float4* o = (float4*)(out + (size_t)t * DDIM);
    int i = threadIdx.x;
    float4 a = y0[i], b = y1[i];
    o[i] = make_float4(p0 * a.x + p1 * b.x, p0 * a.y + p1 * b.y,
                       p0 * a.z + p1 * b.z, p0 * a.w + p1 * b.w);
}

// ---------------------------------------------------------------------------
// GEMM tile geometry: 256 threads (8 warps, 4x2), 2 CTAs/SM.
//   K_TILE = 64 halves (128 B + 16 pad -> 144 B row stride), 3 stages.
// ---------------------------------------------------------------------------
#define KT      64
#define RSTRB   144
#define G_SA    (128 * RSTRB)
#define STAGE   (2 * G_SA)             // 36864
#define SMEM_DYN (3 * STAGE)           // 110592

// ---------------------------------------------------------------------------
// GEMM1 + SwiGLU. BM=128 rows, BF=64 f-cols (x2 matrices). Warp: 32 x 32 x2.
// B fragments via ldmatrix x4 (two n-groups per instruction).
// ---------------------------------------------------------------------------
__global__ __launch_bounds__(256, 2)
void gemm1_kernel() {
    int e = blockIdx.z;
    int cnt = g_counts[e];
    int base = blockIdx.y * 128;
    if (base >= cnt) return;
    int off = g_offsets[e];
    int f0 = blockIdx.x * 64;

    extern __shared__ char sm[];
    __shared__ int toks[128];
    int tid = threadIdx.x;
    if (tid < 128)
        toks[tid] = (base + tid < cnt) ? g_rowTok[off + base + tid] : -1;
    __syncthreads();

    const __half* W1e = g_W1h + ((size_t)e * FDIM + f0) * DDIM;
    const __half* W2e = g_W2h + ((size_t)e * FDIM + f0) * DDIM;

    int w = tid >> 5, lane = tid & 31;
    int wm = w >> 1, wn = w & 1;
    int g = lane >> 2, tig = lane & 3;

    uint32_t smbase = smem_u32(sm);
    uint32_t arow  = (uint32_t)((wm * 32 + (lane & 15)) * RSTRB + (lane >> 4) * 16);
    // x4 B address: lanes 0-7 (n-grp0,k0), 8-15 (n-grp0,k1), 16-23 (n-grp1,k0), 24-31 (n-grp1,k1)
    uint32_t brow4 = (uint32_t)((wn * 32 + (lane & 7) + ((lane >> 4) & 1) * 8) * RSTRB
                                + ((lane >> 3) & 1) * 16);

    float acc1[2][4][4], acc2[2][4][4];
    #pragma unroll
    for (int mi = 0; mi < 2; mi++)
        #pragma unroll
        for (int ni = 0; ni < 4; ni++)
            #pragma unroll
            for (int q = 0; q < 4; q++) { acc1[mi][ni][q] = 0.f; acc2[mi][ni][q] = 0.f; }

    const int NKT = DDIM / KT;   // 16

    auto load_stage = [&](int s, int k0) {
        char* smA = sm + s * STAGE;
        char* smB = smA + G_SA;
        #pragma unroll
        for (int j = 0; j < 4; j++) {
            int slot = tid + j * 256;
            int row = slot >> 3, q = slot & 7;
            int tok = toks[row];
            const __half* src = g_xh + (size_t)(tok >= 0 ? tok : 0) * DDIM + k0 + q * 8;
            cp16(smA + row * RSTRB + q * 16, src, tok >= 0 ? 16 : 0);
        }
        #pragma unroll
        for (int j = 0; j < 4; j++) {
            int slot = tid + j * 256;
            int r = slot >> 3, q = slot & 7;
            int mat = r >> 6, rw = r & 63;
            const __half* src = (mat ? W2e : W1e) + (size_t)rw * DDIM + k0 + q * 8;
            cp16(smB + r * RSTRB + q * 16, src, 16);
        }
    };

    load_stage(0, 0);  CP_COMMIT();
    load_stage(1, KT); CP_COMMIT();

    for (int kt = 0; kt < NKT; kt++) {
        if (kt + 1 < NKT) CP_WAIT(1); else CP_WAIT(0);
        __syncthreads();
        if (kt + 2 < NKT) { load_stage((kt + 2) % 3, (kt + 2) * KT); CP_COMMIT(); }

        int s = kt % 3;
        uint32_t sa = smbase + s * STAGE;
        uint32_t ub = sa + G_SA;

        #pragma unroll
        for (int ks = 0; ks < 4; ks++) {
            // --- 6 batched ldmatrix ---
            uint32_t a0[4], a1[4], b1f[2][4], b2f[2][4];
            ldsm4(a0, sa + arow + ks * 32);
            ldsm4(a1, sa + arow + 16 * RSTRB + ks * 32);
            #pragma unroll
            for (int n2 = 0; n2 < 2; n2++) {
                ldsm4(b1f[n2], ub + brow4 + n2 * 16 * RSTRB + ks * 32);
                ldsm4(b2f[n2], ub + brow4 + (64 + n2 * 16) * RSTRB + ks * 32);
            }
            // --- 16 back-to-back MMAs ---
            #pragma unroll
            for (int n2 = 0; n2 < 2; n2++) {
                #pragma unroll
                for (int h = 0; h < 2; h++) {
                    mma_f16(acc1[0][n2 * 2 + h], a0, b1f[n2][2 * h], b1f[n2][2 * h + 1]);
                    mma_f16(acc1[1][n2 * 2 + h], a1, b1f[n2][2 * h], b1f[n2][2 * h + 1]);
                    mma_f16(acc2[0][n2 * 2 + h], a0, b2f[n2][2 * h], b2f[n2][2 * h + 1]);
                    mma_f16(acc2[1][n2 * 2 + h], a1, b2f[n2][2 * h], b2f[n2][2 * h + 1]);
                }
            }
        }
    }

    // Epilogue: SwiGLU -> Hh (fp16)
    #pragma unroll
    for (int mi = 0; mi < 2; mi++) {
        int r0 = base + wm * 32 + mi * 16 + g;
        #pragma unroll
        for (int ni = 0; ni < 4; ni++) {
            int col = f0 + wn * 32 + ni * 8 + tig * 2;
            #pragma unroll
            for (int half = 0; half < 2; half++) {
                int row = r0 + half * 8;
                if (row < cnt) {
                    float h1a = acc1[mi][ni][half * 2 + 0];
                    float h1b = acc1[mi][ni][half * 2 + 1];
                    float h2a = acc2[mi][ni][half * 2 + 0];
                    float h2b = acc2[mi][ni][half * 2 + 1];
                    float oa = h1a / (1.f + __expf(-h1a)) * h2a;
                    float ob = h1b / (1.f + __expf(-h1b)) * h2b;
                    *(__half2*)(g_Hh + (size_t)(off + row) * FDIM + col) =
                        __floats2half2_rn(oa, ob);
                }
            }
        }
    }
}

// ---------------------------------------------------------------------------
// GEMM2: Y = H . W3^T. BM=128 rows, BN=128 d-cols. Warp: 32 x 64.
// ---------------------------------------------------------------------------
__global__ __launch_bounds__(256, 2)
void gemm2_kernel() {
    int e = blockIdx.z;
    int cnt = g_counts[e];
    int base = blockIdx.y * 128;
    if (base >= cnt) return;
    int off = g_offsets[e];
    int d0 = blockIdx.x * 128;

    extern __shared__ char sm[];
    int tid = threadIdx.x;

    const __half* W3e = g_W3h + ((size_t)e * DDIM + d0) * FDIM;
    const __half* Ab  = g_Hh + (size_t)(off + base) * FDIM;
    int arows = cnt - base;

    int w = tid >> 5, lane = tid & 31;
    int wm = w >> 1, wn = w & 1;
    int g = lane >> 2, tig = lane & 3;

    uint32_t smbase = smem_u32(sm);
    uint32_t arow  = (uint32_t)((wm * 32 + (lane & 15)) * RSTRB + (lane >> 4) * 16);
    uint32_t brow4 = (uint32_t)((wn * 64 + (lane & 7) + ((lane >> 4) & 1) * 8) * RSTRB
                                + ((lane >> 3) & 1) * 16);

    float acc[2][8][4];
    #pragma unroll
    for (int mi = 0; mi < 2; mi++)
        #pragma unroll
        for (int ni = 0; ni < 8; ni++)
            #pragma unroll
            for (int q = 0; q < 4; q++) acc[mi][ni][q] = 0.f;

    const int NKT = FDIM / KT;   // 32

    auto load_stage = [&](int s, int k0) {
        char* smA = sm + s * STAGE;
        char* smB = smA + G_SA;
        #pragma unroll
        for (int j = 0; j < 4; j++) {
            int slot = tid + j * 256;
            int row = slot >> 3, q = slot & 7;
            const __half* src = Ab + (size_t)(row < arows ? row : 0) * FDIM + k0 + q * 8;
            cp16(smA + row * RSTRB + q * 16, src, row < arows ? 16 : 0);
        }
        #pragma unroll
        for (int j = 0; j < 4; j++) {
            int slot = tid + j * 256;
            int r = slot >> 3, q = slot & 7;
            const __half* src = W3e + (size_t)r * FDIM + k0 + q * 8;
            cp16(smB + r * RSTRB + q * 16, src, 16);
        }
    };

    load_stage(0, 0);  CP_COMMIT();
    load_stage(1, KT); CP_COMMIT();

    for (int kt = 0; kt < NKT; kt++) {
        if (kt + 1 < NKT) CP_WAIT(1); else CP_WAIT(0);
        __syncthreads();
        if (kt + 2 < NKT) { load_stage((kt + 2) % 3, (kt + 2) * KT); CP_COMMIT(); }

        int s = kt % 3;
        uint32_t sa = smbase + s * STAGE;
        uint32_t ub = sa + G_SA;

        #pragma unroll
        for (int ks = 0; ks < 4; ks++) {
            uint32_t a0[4], a1[4], bf[4][4];
            ldsm4(a0, sa + arow + ks * 32);
            ldsm4(a1, sa + arow + 16 * RSTRB + ks * 32);
            #pragma unroll
            for (int n2 = 0; n2 < 4; n2++)
                ldsm4(bf[n2], ub + brow4 + n2 * 16 * RSTRB + ks * 32);
            #pragma unroll
            for (int n2 = 0; n2 < 4; n2++) {
                #pragma unroll
                for (int h = 0; h < 2; h++) {
                    mma_f16(acc[0][n2 * 2 + h], a0, bf[n2][2 * h], bf[n2][2 * h + 1]);
                    mma_f16(acc[1][n2 * 2 + h], a1, bf[n2][2 * h], bf[n2][2 * h + 1]);
                }
            }
        }
    }

    #pragma unroll
    for (int mi = 0; mi < 2; mi++) {
        int r0 = base + wm * 32 + mi * 16 + g;
        #pragma unroll
        for (int ni = 0; ni < 8; ni++) {
            int col = d0 + wn * 64 + ni * 8 + tig * 2;
            #pragma unroll
            for (int half = 0; half < 2; half++) {
                int row = r0 + half * 8;
                if (row < cnt) {
                    *(float2*)(g_Y + (size_t)(off + row) * DDIM + col) =
                        make_float2(acc[mi][ni][half * 2 + 0],
                                    acc[mi][ni][half * 2 + 1]);
                }
            }
        }
    }
}

// ---------------------------------------------------------------------------
// Entry point — gemm1 stays at launch index 3 (the ncu-sampled slot)
// ---------------------------------------------------------------------------
extern "C" void kernel_launch(void* const* d_in, const int* in_sizes, int n_in,
                              void* d_out, int out_size) {
    (void)in_sizes; (void)n_in; (void)out_size;
    const float* x  = (const float*)d_in[0];
    const float* Wg = (const float*)d_in[1];
    const float* W1 = (const float*)d_in[2];
    const float* W2 = (const float*)d_in[3];
    const float* W3 = (const float*)d_in[4];
    float* out = (float*)d_out;

    cudaFuncSetAttribute(gemm1_kernel, cudaFuncAttributeMaxDynamicSharedMemorySize, SMEM_DYN);
    cudaFuncSetAttribute(gemm2_kernel, cudaFuncAttributeMaxDynamicSharedMemorySize, SMEM_DYN);

    convert_kernel<<<CVT_TOTAL / 256, 256>>>(x, W1, W2, W3);        // 0
    gating_kernel<<<TKN, 256>>>(x, Wg);                             // 1
    scatter_kernel<<<TKN / 256, 256>>>();                           // 2
    gemm1_kernel<<<dim3(FDIM / 64, TKN / 128, NEXP), 256, SMEM_DYN>>>();   // 3 (profiled)
    gemm2_kernel<<<dim3(DDIM / 128, TKN / 128, NEXP), 256, SMEM_DYN>>>();  // 4
    combine_kernel<<<TKN, 256>>>(out);                              // 5
}

// round 8
// speedup vs baseline: 3.0814x; 1.0671x over previous
#include <cuda_runtime.h>
#include <cuda_fp16.h>
#include <cstdint>
#include <math.h>

// Problem constants
#define TKN   4096
#define DDIM  1024
#define FDIM  2048
#define NEXP  8
#define NASS  (TKN * 2)

// ---------------------------------------------------------------------------
// Scratch (device globals)
// ---------------------------------------------------------------------------
__device__ int   g_counts[NEXP];
__device__ int   g_offsets[NEXP + 1];
__device__ int   g_cursor[NEXP];
__device__ int   g_rowTok[NASS];
__device__ int   g_assignRow[NASS];
__device__ float g_probs[NASS];
__device__ int   g_topE[NASS];

__device__ __align__(16) __half g_xh[(size_t)TKN * DDIM];
__device__ __align__(16) __half g_W1h[(size_t)NEXP * FDIM * DDIM];
__device__ __align__(16) __half g_W2h[(size_t)NEXP * FDIM * DDIM];
__device__ __align__(16) __half g_W3h[(size_t)NEXP * DDIM * FDIM];
__device__ __align__(16) __half g_Hh[(size_t)NASS * FDIM];
__device__ __align__(16) float  g_Y[(size_t)NASS * DDIM];

// ---------------------------------------------------------------------------
// Helpers
// ---------------------------------------------------------------------------
__device__ __forceinline__ uint32_t smem_u32(const void* p) {
    uint32_t a;
    asm("{ .reg .u64 t; cvta.to.shared.u64 t, %1; cvt.u32.u64 %0, t; }" : "=r"(a) : "l"(p));
    return a;
}
__device__ __forceinline__ void cp16(void* dst, const void* src, int zfill) {
    uint32_t d = smem_u32(dst);
    asm volatile("cp.async.cg.shared.global [%0], [%1], 16, %2;"
                 :: "r"(d), "l"(src), "r"(zfill) : "memory");
}
#define CP_COMMIT() asm volatile("cp.async.commit_group;" ::: "memory")
#define CP_WAIT(n)  asm volatile("cp.async.wait_group %0;" :: "n"(n) : "memory")

__device__ __forceinline__ void mma_f16(float* c, const uint32_t* a,
                                        uint32_t b0, uint32_t b1) {
    asm volatile(
        "mma.sync.aligned.m16n8k16.row.col.f32.f16.f16.f32 "
        "{%0,%1,%2,%3}, {%4,%5,%6,%7}, {%8,%9}, {%0,%1,%2,%3};"
        : "+f"(c[0]), "+f"(c[1]), "+f"(c[2]), "+f"(c[3])
        : "r"(a[0]), "r"(a[1]), "r"(a[2]), "r"(a[3]), "r"(b0), "r"(b1));
}
__device__ __forceinline__ void ldsm4(uint32_t* r, uint32_t a) {
    asm volatile("ldmatrix.sync.aligned.m8n8.x4.shared.b16 {%0,%1,%2,%3}, [%4];"
                 : "=r"(r[0]), "=r"(r[1]), "=r"(r[2]), "=r"(r[3]) : "r"(a));
}

// ---------------------------------------------------------------------------
// Fused fp32->fp16 convert + zero routing counters.
// Pair-granularity: 2 float4 loads -> 1 uint4 (16B) store; 2 pairs per thread.
// ---------------------------------------------------------------------------
#define X4 (TKN * DDIM / 4)
#define W4 (NEXP * FDIM * DDIM / 4)
#define CVT_TOTAL (X4 + 3 * W4)
#define XP ((long)X4 / 2)
#define WP ((long)W4 / 2)
#define CVT_PAIRS (XP + 3 * WP)
#define CVT_BLOCKS ((int)(CVT_PAIRS / 512))

__global__ __launch_bounds__(256) void convert_kernel(
    const float* __restrict__ x, const float* __restrict__ W1,
    const float* __restrict__ W2, const float* __restrict__ W3) {
    if (blockIdx.x == 0 && threadIdx.x < NEXP) {
        g_counts[threadIdx.x] = 0;
        g_cursor[threadIdx.x] = 0;
    }
    #pragma unroll
    for (int u = 0; u < 2; u++) {
        long p = (long)blockIdx.x * 512 + u * 256 + threadIdx.x;
        if (p >= CVT_PAIRS) return;
        const float4* s; uint4* d; long j;
        if (p < XP)               { s = (const float4*)x;  d = (uint4*)g_xh;  j = p; }
        else if (p < XP + WP)     { s = (const float4*)W1; d = (uint4*)g_W1h; j = p - XP; }
        else if (p < XP + 2 * WP) { s = (const float4*)W2; d = (uint4*)g_W2h; j = p - XP - WP; }
        else                      { s = (const float4*)W3; d = (uint4*)g_W3h; j = p - XP - 2 * WP; }
        float4 a = s[2 * j], b = s[2 * j + 1];
        __half2 h0 = __floats2half2_rn(a.x, a.y);
        __half2 h1 = __floats2half2_rn(a.z, a.w);
        __half2 h2 = __floats2half2_rn(b.x, b.y);
        __half2 h3 = __floats2half2_rn(b.z, b.w);
        uint4 o;
        o.x = *reinterpret_cast<uint32_t*>(&h0);
        o.y = *reinterpret_cast<uint32_t*>(&h1);
        o.z = *reinterpret_cast<uint32_t*>(&h2);
        o.w = *reinterpret_cast<uint32_t*>(&h3);
        d[j] = o;
    }
}

// ---------------------------------------------------------------------------
// Gating
// ---------------------------------------------------------------------------
__global__ __launch_bounds__(256) void gating_kernel(
    const float* __restrict__ x, const float* __restrict__ Wg) {
    int t = blockIdx.x;
    __shared__ float xs[DDIM];
    __shared__ float sc[NEXP];
    for (int i = threadIdx.x; i < DDIM; i += 256)
        xs[i] = x[(size_t)t * DDIM + i];
    __syncthreads();
    int w = threadIdx.x >> 5, lane = threadIdx.x & 31;
    const float* wg = Wg + (size_t)w * DDIM;
    float acc = 0.f;
    #pragma unroll 8
    for (int i = lane; i < DDIM; i += 32) acc += xs[i] * wg[i];
    #pragma unroll
    for (int o = 16; o; o >>= 1) acc += __shfl_xor_sync(0xFFFFFFFFu, acc, o);
    if (lane == 0) sc[w] = acc;
    __syncthreads();
    if (threadIdx.x == 0) {
        int e0 = 0; float s0 = sc[0];
        #pragma unroll
        for (int e = 1; e < NEXP; e++)
            if (sc[e] > s0) { s0 = sc[e]; e0 = e; }
        int e1 = -1; float s1 = -1e30f;
        #pragma unroll
        for (int e = 0; e < NEXP; e++)
            if (e != e0 && sc[e] > s1) { s1 = sc[e]; e1 = e; }
        float z = expf(s1 - s0);
        float inv = 1.f / (1.f + z);
        g_topE[2 * t] = e0;  g_topE[2 * t + 1] = e1;
        g_probs[2 * t] = inv; g_probs[2 * t + 1] = z * inv;
        atomicAdd(&g_counts[e0], 1);
        atomicAdd(&g_counts[e1], 1);
    }
}

// ---------------------------------------------------------------------------
// Scatter (with local scan of the 8 expert counts)
// ---------------------------------------------------------------------------
__global__ __launch_bounds__(256) void scatter_kernel() {
    __shared__ int soff[NEXP];
    if (threadIdx.x < NEXP) {
        int o = 0;
        for (int e = 0; e < threadIdx.x; e++) o += g_counts[e];
        soff[threadIdx.x] = o;
        if (blockIdx.x == 0) {
            g_offsets[threadIdx.x] = o;
            if (threadIdx.x == NEXP - 1) g_offsets[NEXP] = o + g_counts[NEXP - 1];
        }
    }
    __syncthreads();
    int t = blockIdx.x * blockDim.x + threadIdx.x;
    if (t >= TKN) return;
    #pragma unroll
    for (int k = 0; k < 2; k++) {
        int e = g_topE[2 * t + k];
        int pos = soff[e] + atomicAdd(&g_cursor[e], 1);
        g_rowTok[pos] = t;
        g_assignRow[2 * t + k] = pos;
    }
}

__global__ __launch_bounds__(256) void combine_kernel(float* __restrict__ out) {
    int t = blockIdx.x;
    float p0 = g_probs[2 * t], p1 = g_probs[2 * t + 1];
    const float4* y0 = (const float4*)(g_Y + (size_t)g_assignRow[2 * t] * DDIM);
    const float4* y1 = (const float4*)(g_Y + (size_t)g_assignRow[2 * t + 1] * DDIM);
    float4* o = (float4*)(out + (size_t)t * DDIM);
    int i = threadIdx.x;
    float4 a = y0[i], b = y1[i];
    o[i] = make_float4(p0 * a.x + p1 * b.x, p0 * a.y + p1 * b.y,
                       p0 * a.z + p1 * b.z, p0 * a.w + p1 * b.w);
}

// ---------------------------------------------------------------------------
// GEMM tile geometry: 256 threads (8 warps, 4x2), 2 CTAs/SM.
//   K_TILE = 64 halves (128 B + 16 pad -> 144 B row stride), 3 stages.
// ---------------------------------------------------------------------------
#define KT      64
#define RSTRB   144
#define G_SA    (128 * RSTRB)
#define STAGE   (2 * G_SA)             // 36864
#define SMEM_DYN (3 * STAGE)           // 110592

// ---------------------------------------------------------------------------
// GEMM1 + SwiGLU. BM=128 rows, BF=64 f-cols (x2 matrices). Warp: 32 x 32 x2.
// Loads for stage kt+2 issued AFTER math(kt) (barrier at top still protects).
// ---------------------------------------------------------------------------
__global__ __launch_bounds__(256, 2)
void gemm1_kernel() {
    int e = blockIdx.z;
    int cnt = g_counts[e];
    int base = blockIdx.y * 128;
    if (base >= cnt) return;
    int off = g_offsets[e];
    int f0 = blockIdx.x * 64;

    extern __shared__ char sm[];
    __shared__ int toks[128];
    int tid = threadIdx.x;
    if (tid < 128)
        toks[tid] = (base + tid < cnt) ? g_rowTok[off + base + tid] : -1;
    __syncthreads();

    const __half* W1e = g_W1h + ((size_t)e * FDIM + f0) * DDIM;
    const __half* W2e = g_W2h + ((size_t)e * FDIM + f0) * DDIM;

    int w = tid >> 5, lane = tid & 31;
    int wm = w >> 1, wn = w & 1;
    int g = lane >> 2, tig = lane & 3;

    uint32_t smbase = smem_u32(sm);
    uint32_t arow  = (uint32_t)((wm * 32 + (lane & 15)) * RSTRB + (lane >> 4) * 16);
    uint32_t brow4 = (uint32_t)((wn * 32 + (lane & 7) + ((lane >> 4) & 1) * 8) * RSTRB
                                + ((lane >> 3) & 1) * 16);

    float acc1[2][4][4], acc2[2][4][4];
    #pragma unroll
    for (int mi = 0; mi < 2; mi++)
        #pragma unroll
        for (int ni = 0; ni < 4; ni++)
            #pragma unroll
            for (int q = 0; q < 4; q++) { acc1[mi][ni][q] = 0.f; acc2[mi][ni][q] = 0.f; }

    const int NKT = DDIM / KT;   // 16

    auto load_stage = [&](int s, int k0) {
        char* smA = sm + s * STAGE;
        char* smB = smA + G_SA;
        #pragma unroll
        for (int j = 0; j < 4; j++) {
            int slot = tid + j * 256;
            int row = slot >> 3, q = slot & 7;
            int tok = toks[row];
            const __half* src = g_xh + (size_t)(tok >= 0 ? tok : 0) * DDIM + k0 + q * 8;
            cp16(smA + row * RSTRB + q * 16, src, tok >= 0 ? 16 : 0);
        }
        #pragma unroll
        for (int j = 0; j < 4; j++) {
            int slot = tid + j * 256;
            int r = slot >> 3, q = slot & 7;
            int mat = r >> 6, rw = r & 63;
            const __half* src = (mat ? W2e : W1e) + (size_t)rw * DDIM + k0 + q * 8;
            cp16(smB + r * RSTRB + q * 16, src, 16);
        }
    };

    load_stage(0, 0);  CP_COMMIT();
    load_stage(1, KT); CP_COMMIT();

    for (int kt = 0; kt < NKT; kt++) {
        if (kt + 1 < NKT) CP_WAIT(1); else CP_WAIT(0);
        __syncthreads();

        int s = kt % 3;
        uint32_t sa = smbase + s * STAGE;
        uint32_t ub = sa + G_SA;

        #pragma unroll
        for (int ks = 0; ks < 4; ks++) {
            uint32_t a0[4], a1[4], b1f[2][4], b2f[2][4];
            ldsm4(a0, sa + arow + ks * 32);
            ldsm4(a1, sa + arow + 16 * RSTRB + ks * 32);
            #pragma unroll
            for (int n2 = 0; n2 < 2; n2++) {
                ldsm4(b1f[n2], ub + brow4 + n2 * 16 * RSTRB + ks * 32);
                ldsm4(b2f[n2], ub + brow4 + (64 + n2 * 16) * RSTRB + ks * 32);
            }
            #pragma unroll
            for (int n2 = 0; n2 < 2; n2++) {
                #pragma unroll
                for (int h = 0; h < 2; h++) {
                    mma_f16(acc1[0][n2 * 2 + h], a0, b1f[n2][2 * h], b1f[n2][2 * h + 1]);
                    mma_f16(acc1[1][n2 * 2 + h], a1, b1f[n2][2 * h], b1f[n2][2 * h + 1]);
                    mma_f16(acc2[0][n2 * 2 + h], a0, b2f[n2][2 * h], b2f[n2][2 * h + 1]);
                    mma_f16(acc2[1][n2 * 2 + h], a1, b2f[n2][2 * h], b2f[n2][2 * h + 1]);
                }
            }
        }

        // Issue next-next stage loads after math (barrier above protects reuse)
        if (kt + 2 < NKT) { load_stage((kt + 2) % 3, (kt + 2) * KT); CP_COMMIT(); }
    }

    // Epilogue: SwiGLU -> Hh (fp16)
    #pragma unroll
    for (int mi = 0; mi < 2; mi++) {
        int r0 = base + wm * 32 + mi * 16 + g;
        #pragma unroll
        for (int ni = 0; ni < 4; ni++) {
            int col = f0 + wn * 32 + ni * 8 + tig * 2;
            #pragma unroll
            for (int half = 0; half < 2; half++) {
                int row = r0 + half * 8;
                if (row < cnt) {
                    float h1a = acc1[mi][ni][half * 2 + 0];
                    float h1b = acc1[mi][ni][half * 2 + 1];
                    float h2a = acc2[mi][ni][half * 2 + 0];
                    float h2b = acc2[mi][ni][half * 2 + 1];
                    float oa = h1a / (1.f + __expf(-h1a)) * h2a;
                    float ob = h1b / (1.f + __expf(-h1b)) * h2b;
                    *(__half2*)(g_Hh + (size_t)(off + row) * FDIM + col) =
                        __floats2half2_rn(oa, ob);
                }
            }
        }
    }
}

// ---------------------------------------------------------------------------
// GEMM2: Y = H . W3^T. BM=128 rows, BN=128 d-cols. Warp: 32 x 64.
// ---------------------------------------------------------------------------
__global__ __launch_bounds__(256, 2)
void gemm2_kernel() {
    int e = blockIdx.z;
    int cnt = g_counts[e];
    int base = blockIdx.y * 128;
    if (base >= cnt) return;
    int off = g_offsets[e];
    int d0 = blockIdx.x * 128;

    extern __shared__ char sm[];
    int tid = threadIdx.x;

    const __half* W3e = g_W3h + ((size_t)e * DDIM + d0) * FDIM;
    const __half* Ab  = g_Hh + (size_t)(off + base) * FDIM;
    int arows = cnt - base;

    int w = tid >> 5, lane = tid & 31;
    int wm = w >> 1, wn = w & 1;
    int g = lane >> 2, tig = lane & 3;

    uint32_t smbase = smem_u32(sm);
    uint32_t arow  = (uint32_t)((wm * 32 + (lane & 15)) * RSTRB + (lane >> 4) * 16);
    uint32_t brow4 = (uint32_t)((wn * 64 + (lane & 7) + ((lane >> 4) & 1) * 8) * RSTRB
                                + ((lane >> 3) & 1) * 16);

    float acc[2][8][4];
    #pragma unroll
    for (int mi = 0; mi < 2; mi++)
        #pragma unroll
        for (int ni = 0; ni < 8; ni++)
            #pragma unroll
            for (int q = 0; q < 4; q++) acc[mi][ni][q] = 0.f;

    const int NKT = FDIM / KT;   // 32

    auto load_stage = [&](int s, int k0) {
        char* smA = sm + s * STAGE;
        char* smB = smA + G_SA;
        #pragma unroll
        for (int j = 0; j < 4; j++) {
            int slot = tid + j * 256;
            int row = slot >> 3, q = slot & 7;
            const __half* src = Ab + (size_t)(row < arows ? row : 0) * FDIM + k0 + q * 8;
            cp16(smA + row * RSTRB + q * 16, src, row < arows ? 16 : 0);
        }
        #pragma unroll
        for (int j = 0; j < 4; j++) {
            int slot = tid + j * 256;
            int r = slot >> 3, q = slot & 7;
            const __half* src = W3e + (size_t)r * FDIM + k0 + q * 8;
            cp16(smB + r * RSTRB + q * 16, src, 16);
        }
    };

    load_stage(0, 0);  CP_COMMIT();
    load_stage(1, KT); CP_COMMIT();

    for (int kt = 0; kt < NKT; kt++) {
        if (kt + 1 < NKT) CP_WAIT(1); else CP_WAIT(0);
        __syncthreads();

        int s = kt % 3;
        uint32_t sa = smbase + s * STAGE;
        uint32_t ub = sa + G_SA;

        #pragma unroll
        for (int ks = 0; ks < 4; ks++) {
            uint32_t a0[4], a1[4], bf[4][4];
            ldsm4(a0, sa + arow + ks * 32);
            ldsm4(a1, sa + arow + 16 * RSTRB + ks * 32);
            #pragma unroll
            for (int n2 = 0; n2 < 4; n2++)
                ldsm4(bf[n2], ub + brow4 + n2 * 16 * RSTRB + ks * 32);
            #pragma unroll
            for (int n2 = 0; n2 < 4; n2++) {
                #pragma unroll
                for (int h = 0; h < 2; h++) {
                    mma_f16(acc[0][n2 * 2 + h], a0, bf[n2][2 * h], bf[n2][2 * h + 1]);
                    mma_f16(acc[1][n2 * 2 + h], a1, bf[n2][2 * h], bf[n2][2 * h + 1]);
                }
            }
        }

        if (kt + 2 < NKT) { load_stage((kt + 2) % 3, (kt + 2) * KT); CP_COMMIT(); }
    }

    #pragma unroll
    for (int mi = 0; mi < 2; mi++) {
        int r0 = base + wm * 32 + mi * 16 + g;
        #pragma unroll
        for (int ni = 0; ni < 8; ni++) {
            int col = d0 + wn * 64 + ni * 8 + tig * 2;
            #pragma unroll
            for (int half = 0; half < 2; half++) {
                int row = r0 + half * 8;
                if (row < cnt) {
                    *(float2*)(g_Y + (size_t)(off + row) * DDIM + col) =
                        make_float2(acc[mi][ni][half * 2 + 0],
                                    acc[mi][ni][half * 2 + 1]);
                }
            }
        }
    }
}

// ---------------------------------------------------------------------------
// Entry point — gemm1 stays at launch index 3 (the ncu-sampled slot)
// ---------------------------------------------------------------------------
extern "C" void kernel_launch(void* const* d_in, const int* in_sizes, int n_in,
                              void* d_out, int out_size) {
    (void)in_sizes; (void)n_in; (void)out_size;
    const float* x  = (const float*)d_in[0];
    const float* Wg = (const float*)d_in[1];
    const float* W1 = (const float*)d_in[2];
    const float* W2 = (const float*)d_in[3];
    const float* W3 = (const float*)d_in[4];
    float* out = (float*)d_out;

    cudaFuncSetAttribute(gemm1_kernel, cudaFuncAttributeMaxDynamicSharedMemorySize, SMEM_DYN);
    cudaFuncSetAttribute(gemm2_kernel, cudaFuncAttributeMaxDynamicSharedMemorySize, SMEM_DYN);

    convert_kernel<<<CVT_BLOCKS, 256>>>(x, W1, W2, W3);             // 0
    gating_kernel<<<TKN, 256>>>(x, Wg);                             // 1
    scatter_kernel<<<TKN / 256, 256>>>();                           // 2
    gemm1_kernel<<<dim3(FDIM / 64, TKN / 128, NEXP), 256, SMEM_DYN>>>();   // 3 (profiled)
    gemm2_kernel<<<dim3(DDIM / 128, TKN / 128, NEXP), 256, SMEM_DYN>>>();  // 4
    combine_kernel<<<TKN, 256>>>(out);                              // 5
}

// round 9
// speedup vs baseline: 3.0961x; 1.0048x over previous
#include <cuda_runtime.h>
#include <cuda_fp16.h>
#include <cstdint>
#include <math.h>

// Problem constants
#define TKN   4096
#define DDIM  1024
#define FDIM  2048
#define NEXP  8
#define NASS  (TKN * 2)

// ---------------------------------------------------------------------------
// Scratch (device globals)
// ---------------------------------------------------------------------------
__device__ int   g_counts[NEXP];
__device__ int   g_offsets[NEXP + 1];
__device__ int   g_cursor[NEXP];
__device__ int   g_rowTok[NASS];
__device__ float g_rowProb[NASS];
__device__ float g_probs[NASS];
__device__ int   g_topE[NASS];

__device__ __align__(16) __half g_xh[(size_t)TKN * DDIM];
__device__ __align__(16) __half g_W1h[(size_t)NEXP * FDIM * DDIM];
__device__ __align__(16) __half g_W2h[(size_t)NEXP * FDIM * DDIM];
__device__ __align__(16) __half g_W3h[(size_t)NEXP * DDIM * FDIM];
__device__ __align__(16) __half g_Hh[(size_t)NASS * FDIM];

// ---------------------------------------------------------------------------
// Helpers
// ---------------------------------------------------------------------------
__device__ __forceinline__ uint32_t smem_u32(const void* p) {
    uint32_t a;
    asm("{ .reg .u64 t; cvta.to.shared.u64 t, %1; cvt.u32.u64 %0, t; }" : "=r"(a) : "l"(p));
    return a;
}
__device__ __forceinline__ void cp16(void* dst, const void* src, int zfill) {
    uint32_t d = smem_u32(dst);
    asm volatile("cp.async.cg.shared.global [%0], [%1], 16, %2;"
                 :: "r"(d), "l"(src), "r"(zfill) : "memory");
}
#define CP_COMMIT() asm volatile("cp.async.commit_group;" ::: "memory")
#define CP_WAIT(n)  asm volatile("cp.async.wait_group %0;" :: "n"(n) : "memory")

__device__ __forceinline__ void mma_f16(float* c, const uint32_t* a,
                                        uint32_t b0, uint32_t b1) {
    asm volatile(
        "mma.sync.aligned.m16n8k16.row.col.f32.f16.f16.f32 "
        "{%0,%1,%2,%3}, {%4,%5,%6,%7}, {%8,%9}, {%0,%1,%2,%3};"
        : "+f"(c[0]), "+f"(c[1]), "+f"(c[2]), "+f"(c[3])
        : "r"(a[0]), "r"(a[1]), "r"(a[2]), "r"(a[3]), "r"(b0), "r"(b1));
}
__device__ __forceinline__ void ldsm4(uint32_t* r, uint32_t a) {
    asm volatile("ldmatrix.sync.aligned.m8n8.x4.shared.b16 {%0,%1,%2,%3}, [%4];"
                 : "=r"(r[0]), "=r"(r[1]), "=r"(r[2]), "=r"(r[3]) : "r"(a));
}

// ---------------------------------------------------------------------------
// Fused fp32->fp16 convert + zero routing counters.
// ---------------------------------------------------------------------------
#define X4 (TKN * DDIM / 4)
#define W4 (NEXP * FDIM * DDIM / 4)
#define XP ((long)X4 / 2)
#define WP ((long)W4 / 2)
#define CVT_PAIRS (XP + 3 * WP)
#define CVT_BLOCKS ((int)(CVT_PAIRS / 512))

__global__ __launch_bounds__(256) void convert_kernel(
    const float* __restrict__ x, const float* __restrict__ W1,
    const float* __restrict__ W2, const float* __restrict__ W3) {
    if (blockIdx.x == 0 && threadIdx.x < NEXP) {
        g_counts[threadIdx.x] = 0;
        g_cursor[threadIdx.x] = 0;
    }
    #pragma unroll
    for (int u = 0; u < 2; u++) {
        long p = (long)blockIdx.x * 512 + u * 256 + threadIdx.x;
        if (p >= CVT_PAIRS) return;
        const float4* s; uint4* d; long j;
        if (p < XP)               { s = (const float4*)x;  d = (uint4*)g_xh;  j = p; }
        else if (p < XP + WP)     { s = (const float4*)W1; d = (uint4*)g_W1h; j = p - XP; }
        else if (p < XP + 2 * WP) { s = (const float4*)W2; d = (uint4*)g_W2h; j = p - XP - WP; }
        else                      { s = (const float4*)W3; d = (uint4*)g_W3h; j = p - XP - 2 * WP; }
        float4 a = s[2 * j], b = s[2 * j + 1];
        __half2 h0 = __floats2half2_rn(a.x, a.y);
        __half2 h1 = __floats2half2_rn(a.z, a.w);
        __half2 h2 = __floats2half2_rn(b.x, b.y);
        __half2 h3 = __floats2half2_rn(b.z, b.w);
        uint4 o;
        o.x = *reinterpret_cast<uint32_t*>(&h0);
        o.y = *reinterpret_cast<uint32_t*>(&h1);
        o.z = *reinterpret_cast<uint32_t*>(&h2);
        o.w = *reinterpret_cast<uint32_t*>(&h3);
        d[j] = o;
    }
}

// ---------------------------------------------------------------------------
// Gating
// ---------------------------------------------------------------------------
__global__ __launch_bounds__(256) void gating_kernel(
    const float* __restrict__ x, const float* __restrict__ Wg) {
    int t = blockIdx.x;
    __shared__ float xs[DDIM];
    __shared__ float sc[NEXP];
    for (int i = threadIdx.x; i < DDIM; i += 256)
        xs[i] = x[(size_t)t * DDIM + i];
    __syncthreads();
    int w = threadIdx.x >> 5, lane = threadIdx.x & 31;
    const float* wg = Wg + (size_t)w * DDIM;
    float acc = 0.f;
    #pragma unroll 8
    for (int i = lane; i < DDIM; i += 32) acc += xs[i] * wg[i];
    #pragma unroll
    for (int o = 16; o; o >>= 1) acc += __shfl_xor_sync(0xFFFFFFFFu, acc, o);
    if (lane == 0) sc[w] = acc;
    __syncthreads();
    if (threadIdx.x == 0) {
        int e0 = 0; float s0 = sc[0];
        #pragma unroll
        for (int e = 1; e < NEXP; e++)
            if (sc[e] > s0) { s0 = sc[e]; e0 = e; }
        int e1 = -1; float s1 = -1e30f;
        #pragma unroll
        for (int e = 0; e < NEXP; e++)
            if (e != e0 && sc[e] > s1) { s1 = sc[e]; e1 = e; }
        float z = expf(s1 - s0);
        float inv = 1.f / (1.f + z);
        g_topE[2 * t] = e0;  g_topE[2 * t + 1] = e1;
        g_probs[2 * t] = inv; g_probs[2 * t + 1] = z * inv;
        atomicAdd(&g_counts[e0], 1);
        atomicAdd(&g_counts[e1], 1);
    }
}

// ---------------------------------------------------------------------------
// Scatter (with local scan of the 8 expert counts); records per-row token+prob
// ---------------------------------------------------------------------------
__global__ __launch_bounds__(256) void scatter_kernel() {
    __shared__ int soff[NEXP];
    if (threadIdx.x < NEXP) {
        int o = 0;
        for (int e = 0; e < threadIdx.x; e++) o += g_counts[e];
        soff[threadIdx.x] = o;
        if (blockIdx.x == 0) {
            g_offsets[threadIdx.x] = o;
            if (threadIdx.x == NEXP - 1) g_offsets[NEXP] = o + g_counts[NEXP - 1];
        }
    }
    __syncthreads();
    int t = blockIdx.x * blockDim.x + threadIdx.x;
    if (t >= TKN) return;
    #pragma unroll
    for (int k = 0; k < 2; k++) {
        int e = g_topE[2 * t + k];
        int pos = soff[e] + atomicAdd(&g_cursor[e], 1);
        g_rowTok[pos]  = t;
        g_rowProb[pos] = g_probs[2 * t + k];
    }
}

// ---------------------------------------------------------------------------
// Zero the output buffer (it is poisoned before timing)
// ---------------------------------------------------------------------------
__global__ __launch_bounds__(256) void zero_out_kernel(float* __restrict__ out) {
    int i = blockIdx.x * 256 + threadIdx.x;
    ((float4*)out)[i] = make_float4(0.f, 0.f, 0.f, 0.f);
}

// ---------------------------------------------------------------------------
// GEMM tile geometry: 256 threads (8 warps, 4x2), 2 CTAs/SM.
//   K_TILE = 64 halves (128 B + 16 pad -> 144 B row stride), 3 stages.
// ---------------------------------------------------------------------------
#define KT      64
#define RSTRB   144
#define G_SA    (128 * RSTRB)
#define STAGE   (2 * G_SA)             // 36864
#define SMEM_DYN (3 * STAGE)           // 110592

// ---------------------------------------------------------------------------
// GEMM1 + SwiGLU. BM=128 rows, BF=64 f-cols (x2 matrices). Warp: 32 x 32 x2.
// ---------------------------------------------------------------------------
__global__ __launch_bounds__(256, 2)
void gemm1_kernel() {
    int e = blockIdx.z;
    int cnt = g_counts[e];
    int base = blockIdx.y * 128;
    if (base >= cnt) return;
    int off = g_offsets[e];
    int f0 = blockIdx.x * 64;

    extern __shared__ char sm[];
    __shared__ int toks[128];
    int tid = threadIdx.x;
    if (tid < 128)
        toks[tid] = (base + tid < cnt) ? g_rowTok[off + base + tid] : -1;
    __syncthreads();

    const __half* W1e = g_W1h + ((size_t)e * FDIM + f0) * DDIM;
    const __half* W2e = g_W2h + ((size_t)e * FDIM + f0) * DDIM;

    int w = tid >> 5, lane = tid & 31;
    int wm = w >> 1, wn = w & 1;
    int g = lane >> 2, tig = lane & 3;

    uint32_t smbase = smem_u32(sm);
    uint32_t arow  = (uint32_t)((wm * 32 + (lane & 15)) * RSTRB + (lane >> 4) * 16);
    uint32_t brow4 = (uint32_t)((wn * 32 + (lane & 7) + ((lane >> 4) & 1) * 8) * RSTRB
                                + ((lane >> 3) & 1) * 16);

    float acc1[2][4][4], acc2[2][4][4];
    #pragma unroll
    for (int mi = 0; mi < 2; mi++)
        #pragma unroll
        for (int ni = 0; ni < 4; ni++)
            #pragma unroll
            for (int q = 0; q < 4; q++) { acc1[mi][ni][q] = 0.f; acc2[mi][ni][q] = 0.f; }

    const int NKT = DDIM / KT;   // 16

    auto load_stage = [&](int s, int k0) {
        char* smA = sm + s * STAGE;
        char* smB = smA + G_SA;
        #pragma unroll
        for (int j = 0; j < 4; j++) {
            int slot = tid + j * 256;
            int row = slot >> 3, q = slot & 7;
            int tok = toks[row];
            const __half* src = g_xh + (size_t)(tok >= 0 ? tok : 0) * DDIM + k0 + q * 8;
            cp16(smA + row * RSTRB + q * 16, src, tok >= 0 ? 16 : 0);
        }
        #pragma unroll
        for (int j = 0; j < 4; j++) {
            int slot = tid + j * 256;
            int r = slot >> 3, q = slot & 7;
            int mat = r >> 6, rw = r & 63;
            const __half* src = (mat ? W2e : W1e) + (size_t)rw * DDIM + k0 + q * 8;
            cp16(smB + r * RSTRB + q * 16, src, 16);
        }
    };

    load_stage(0, 0);  CP_COMMIT();
    load_stage(1, KT); CP_COMMIT();

    for (int kt = 0; kt < NKT; kt++) {
        if (kt + 1 < NKT) CP_WAIT(1); else CP_WAIT(0);
        __syncthreads();

        int s = kt % 3;
        uint32_t sa = smbase + s * STAGE;
        uint32_t ub = sa + G_SA;

        #pragma unroll
        for (int ks = 0; ks < 4; ks++) {
            uint32_t a0[4], a1[4], b1f[2][4], b2f[2][4];
            ldsm4(a0, sa + arow + ks * 32);
            ldsm4(a1, sa + arow + 16 * RSTRB + ks * 32);
            #pragma unroll
            for (int n2 = 0; n2 < 2; n2++) {
                ldsm4(b1f[n2], ub + brow4 + n2 * 16 * RSTRB + ks * 32);
                ldsm4(b2f[n2], ub + brow4 + (64 + n2 * 16) * RSTRB + ks * 32);
            }
            #pragma unroll
            for (int n2 = 0; n2 < 2; n2++) {
                #pragma unroll
                for (int h = 0; h < 2; h++) {
                    mma_f16(acc1[0][n2 * 2 + h], a0, b1f[n2][2 * h], b1f[n2][2 * h + 1]);
                    mma_f16(acc1[1][n2 * 2 + h], a1, b1f[n2][2 * h], b1f[n2][2 * h + 1]);
                    mma_f16(acc2[0][n2 * 2 + h], a0, b2f[n2][2 * h], b2f[n2][2 * h + 1]);
                    mma_f16(acc2[1][n2 * 2 + h], a1, b2f[n2][2 * h], b2f[n2][2 * h + 1]);
                }
            }
        }

        if (kt + 2 < NKT) { load_stage((kt + 2) % 3, (kt + 2) * KT); CP_COMMIT(); }
    }

    // Epilogue: SwiGLU -> Hh (fp16)
    #pragma unroll
    for (int mi = 0; mi < 2; mi++) {
        int r0 = base + wm * 32 + mi * 16 + g;
        #pragma unroll
        for (int ni = 0; ni < 4; ni++) {
            int col = f0 + wn * 32 + ni * 8 + tig * 2;
            #pragma unroll
            for (int half = 0; half < 2; half++) {
                int row = r0 + half * 8;
                if (row < cnt) {
                    float h1a = acc1[mi][ni][half * 2 + 0];
                    float h1b = acc1[mi][ni][half * 2 + 1];
                    float h2a = acc2[mi][ni][half * 2 + 0];
                    float h2b = acc2[mi][ni][half * 2 + 1];
                    float oa = h1a / (1.f + __expf(-h1a)) * h2a;
                    float ob = h1b / (1.f + __expf(-h1b)) * h2b;
                    *(__half2*)(g_Hh + (size_t)(off + row) * FDIM + col) =
                        __floats2half2_rn(oa, ob);
                }
            }
        }
    }
}

// ---------------------------------------------------------------------------
// GEMM2 + fused combine: out[tok] += prob * (H[row] . W3[e]^T)
// BM=128 rows, BN=128 d-cols. Warp: 32 x 64.
// Exactly two assignments contribute per out element; two-term fp add is
// commutative, so atomicAdd order cannot change the result.
// ---------------------------------------------------------------------------
__global__ __launch_bounds__(256, 2)
void gemm2_kernel(float* __restrict__ out) {
    int e = blockIdx.z;
    int cnt = g_counts[e];
    int base = blockIdx.y * 128;
    if (base >= cnt) return;
    int off = g_offsets[e];
    int d0 = blockIdx.x * 128;

    extern __shared__ char sm[];
    int tid = threadIdx.x;

    const __half* W3e = g_W3h + ((size_t)e * DDIM + d0) * FDIM;
    const __half* Ab  = g_Hh + (size_t)(off + base) * FDIM;
    int arows = cnt - base;

    int w = tid >> 5, lane = tid & 31;
    int wm = w >> 1, wn = w & 1;
    int g = lane >> 2, tig = lane & 3;

    uint32_t smbase = smem_u32(sm);
    uint32_t arow  = (uint32_t)((wm * 32 + (lane & 15)) * RSTRB + (lane >> 4) * 16);
    uint32_t brow4 = (uint32_t)((wn * 64 + (lane & 7) + ((lane >> 4) & 1) * 8) * RSTRB
                                + ((lane >> 3) & 1) * 16);

    float acc[2][8][4];
    #pragma unroll
    for (int mi = 0; mi < 2; mi++)
        #pragma unroll
        for (int ni = 0; ni < 8; ni++)
            #pragma unroll
            for (int q = 0; q < 4; q++) acc[mi][ni][q] = 0.f;

    const int NKT = FDIM / KT;   // 32

    auto load_stage = [&](int s, int k0) {
        char* smA = sm + s * STAGE;
        char* smB = smA + G_SA;
        #pragma unroll
        for (int j = 0; j < 4; j++) {
            int slot = tid + j * 256;
            int row = slot >> 3, q = slot & 7;
            const __half* src = Ab + (size_t)(row < arows ? row : 0) * FDIM + k0 + q * 8;
            cp16(smA + row * RSTRB + q * 16, src, row < arows ? 16 : 0);
        }
        #pragma unroll
        for (int j = 0; j < 4; j++) {
            int slot = tid + j * 256;
            int r = slot >> 3, q = slot & 7;
            const __half* src = W3e + (size_t)r * FDIM + k0 + q * 8;
            cp16(smB + r * RSTRB + q * 16, src, 16);
        }
    };

    load_stage(0, 0);  CP_COMMIT();
    load_stage(1, KT); CP_COMMIT();

    for (int kt = 0; kt < NKT; kt++) {
        if (kt + 1 < NKT) CP_WAIT(1); else CP_WAIT(0);
        __syncthreads();

        int s = kt % 3;
        uint32_t sa = smbase + s * STAGE;
        uint32_t ub = sa + G_SA;

        #pragma unroll
        for (int ks = 0; ks < 4; ks++) {
            uint32_t a0[4], a1[4], bf[4][4];
            ldsm4(a0, sa + arow + ks * 32);
            ldsm4(a1, sa + arow + 16 * RSTRB + ks * 32);
            #pragma unroll
            for (int n2 = 0; n2 < 4; n2++)
                ldsm4(bf[n2], ub + brow4 + n2 * 16 * RSTRB + ks * 32);
            #pragma unroll
            for (int n2 = 0; n2 < 4; n2++) {
                #pragma unroll
                for (int h = 0; h < 2; h++) {
                    mma_f16(acc[0][n2 * 2 + h], a0, bf[n2][2 * h], bf[n2][2 * h + 1]);
                    mma_f16(acc[1][n2 * 2 + h], a1, bf[n2][2 * h], bf[n2][2 * h + 1]);
                }
            }
        }

        if (kt + 2 < NKT) { load_stage((kt + 2) % 3, (kt + 2) * KT); CP_COMMIT(); }
    }

    // Fused combine epilogue: scale by gate prob, atomicAdd into out[token]
    #pragma unroll
    for (int mi = 0; mi < 2; mi++) {
        int rb = wm * 32 + mi * 16 + g;
        #pragma unroll
        for (int half = 0; half < 2; half++) {
            int row = base + rb + half * 8;
            if (row < cnt) {
                int   tok = g_rowTok[off + row];
                float p   = g_rowProb[off + row];
                float* op = out + (size_t)tok * DDIM + d0;
                #pragma unroll
                for (int ni = 0; ni < 8; ni++) {
                    int col = wn * 64 + ni * 8 + tig * 2;
                    atomicAdd(op + col,     p * acc[mi][ni][half * 2 + 0]);
                    atomicAdd(op + col + 1, p * acc[mi][ni][half * 2 + 1]);
                }
            }
        }
    }
}

// ---------------------------------------------------------------------------
// Entry point — gemm1 stays at launch index 3 (the ncu-sampled slot);
// zero_out runs between gemm1 and gemm2 (only needs to precede gemm2).
// ---------------------------------------------------------------------------
extern "C" void kernel_launch(void* const* d_in, const int* in_sizes, int n_in,
                              void* d_out, int out_size) {
    (void)in_sizes; (void)n_in; (void)out_size;
    const float* x  = (const float*)d_in[0];
    const float* Wg = (const float*)d_in[1];
    const float* W1 = (const float*)d_in[2];
    const float* W2 = (const float*)d_in[3];
    const float* W3 = (const float*)d_in[4];
    float* out = (float*)d_out;

    cudaFuncSetAttribute(gemm1_kernel, cudaFuncAttributeMaxDynamicSharedMemorySize, SMEM_DYN);
    cudaFuncSetAttribute(gemm2_kernel, cudaFuncAttributeMaxDynamicSharedMemorySize, SMEM_DYN);

    convert_kernel<<<CVT_BLOCKS, 256>>>(x, W1, W2, W3);             // 0
    gating_kernel<<<TKN, 256>>>(x, Wg);                             // 1
    scatter_kernel<<<TKN / 256, 256>>>();                           // 2
    gemm1_kernel<<<dim3(FDIM / 64, TKN / 128, NEXP), 256, SMEM_DYN>>>();   // 3 (profiled)
    zero_out_kernel<<<TKN * DDIM / 1024, 256>>>(out);               // 4
    gemm2_kernel<<<dim3(DDIM / 128, TKN / 128, NEXP), 256, SMEM_DYN>>>(out); // 5
}

// round 10
// speedup vs baseline: 3.1552x; 1.0191x over previous
#include <cuda_runtime.h>
#include <cuda_fp16.h>
#include <cstdint>
#include <math.h>

// Problem constants
#define TKN   4096
#define DDIM  1024
#define FDIM  2048
#define NEXP  8
#define NASS  (TKN * 2)

// ---------------------------------------------------------------------------
// Scratch (device globals)
// ---------------------------------------------------------------------------
__device__ int   g_counts[NEXP];
__device__ int   g_offsets[NEXP + 1];
__device__ int   g_cursor[NEXP];
__device__ int   g_rowTok[NASS];
__device__ float g_rowProb[NASS];
__device__ float g_probs[NASS];
__device__ int   g_topE[NASS];

__device__ __align__(16) __half g_xh[(size_t)TKN * DDIM];
__device__ __align__(16) __half g_W1h[(size_t)NEXP * FDIM * DDIM];
__device__ __align__(16) __half g_W2h[(size_t)NEXP * FDIM * DDIM];
__device__ __align__(16) __half g_W3h[(size_t)NEXP * DDIM * FDIM];
__device__ __align__(16) __half g_Hh[(size_t)NASS * FDIM];

// ---------------------------------------------------------------------------
// Helpers
// ---------------------------------------------------------------------------
__device__ __forceinline__ uint32_t smem_u32(const void* p) {
    uint32_t a;
    asm("{ .reg .u64 t; cvta.to.shared.u64 t, %1; cvt.u32.u64 %0, t; }" : "=r"(a) : "l"(p));
    return a;
}
__device__ __forceinline__ void cp16(void* dst, const void* src, int zfill) {
    uint32_t d = smem_u32(dst);
    asm volatile("cp.async.cg.shared.global [%0], [%1], 16, %2;"
                 :: "r"(d), "l"(src), "r"(zfill) : "memory");
}
#define CP_COMMIT() asm volatile("cp.async.commit_group;" ::: "memory")
#define CP_WAIT(n)  asm volatile("cp.async.wait_group %0;" :: "n"(n) : "memory")

__device__ __forceinline__ void mma_f16(float* c, const uint32_t* a,
                                        uint32_t b0, uint32_t b1) {
    asm volatile(
        "mma.sync.aligned.m16n8k16.row.col.f32.f16.f16.f32 "
        "{%0,%1,%2,%3}, {%4,%5,%6,%7}, {%8,%9}, {%0,%1,%2,%3};"
        : "+f"(c[0]), "+f"(c[1]), "+f"(c[2]), "+f"(c[3])
        : "r"(a[0]), "r"(a[1]), "r"(a[2]), "r"(a[3]), "r"(b0), "r"(b1));
}
__device__ __forceinline__ void ldsm4(uint32_t* r, uint32_t a) {
    asm volatile("ldmatrix.sync.aligned.m8n8.x4.shared.b16 {%0,%1,%2,%3}, [%4];"
                 : "=r"(r[0]), "=r"(r[1]), "=r"(r[2]), "=r"(r[3]) : "r"(a));
}

// ---------------------------------------------------------------------------
// Weight converts (pair granularity: 2 float4 loads -> 1 uint4 store)
// ---------------------------------------------------------------------------
#define W4 (NEXP * FDIM * DDIM / 4)
#define WP ((long)W4 / 2)

__device__ __forceinline__ void cvt_pair(const float4* s, uint4* d, long j) {
    float4 a = s[2 * j], b = s[2 * j + 1];
    __half2 h0 = __floats2half2_rn(a.x, a.y);
    __half2 h1 = __floats2half2_rn(a.z, a.w);
    __half2 h2 = __floats2half2_rn(b.x, b.y);
    __half2 h3 = __floats2half2_rn(b.z, b.w);
    uint4 o;
    o.x = *reinterpret_cast<uint32_t*>(&h0);
    o.y = *reinterpret_cast<uint32_t*>(&h1);
    o.z = *reinterpret_cast<uint32_t*>(&h2);
    o.w = *reinterpret_cast<uint32_t*>(&h3);
    d[j] = o;
}

__global__ __launch_bounds__(256) void convert_w12_kernel(
    const float* __restrict__ W1, const float* __restrict__ W2) {
    #pragma unroll
    for (int u = 0; u < 2; u++) {
        long p = (long)blockIdx.x * 512 + u * 256 + threadIdx.x;
        if (p < WP)           cvt_pair((const float4*)W1, (uint4*)g_W1h, p);
        else if (p < 2 * WP)  cvt_pair((const float4*)W2, (uint4*)g_W2h, p - WP);
    }
}

__global__ __launch_bounds__(256) void convert_w3_kernel(const float* __restrict__ W3) {
    #pragma unroll
    for (int u = 0; u < 2; u++) {
        long p = (long)blockIdx.x * 512 + u * 256 + threadIdx.x;
        if (p < WP) cvt_pair((const float4*)W3, (uint4*)g_W3h, p);
    }
}

// ---------------------------------------------------------------------------
// Reset routing counters
// ---------------------------------------------------------------------------
__global__ void reset_kernel() {
    if (threadIdx.x < NEXP) {
        g_counts[threadIdx.x] = 0;
        g_cursor[threadIdx.x] = 0;
    }
}

// ---------------------------------------------------------------------------
// Gating: top-2 + softmax + counts; ALSO converts this token's x row to fp16
// ---------------------------------------------------------------------------
__global__ __launch_bounds__(256) void gating_kernel(
    const float* __restrict__ x, const float* __restrict__ Wg) {
    int t = blockIdx.x;
    __shared__ float xs[DDIM];
    __shared__ float sc[NEXP];
    for (int i = threadIdx.x; i < DDIM; i += 256)
        xs[i] = x[(size_t)t * DDIM + i];
    __syncthreads();

    // fused x -> fp16 (row is in smem already)
    {
        int i4 = threadIdx.x * 4;
        __half2 ha = __floats2half2_rn(xs[i4],     xs[i4 + 1]);
        __half2 hb = __floats2half2_rn(xs[i4 + 2], xs[i4 + 3]);
        uint2 o;
        o.x = *reinterpret_cast<uint32_t*>(&ha);
        o.y = *reinterpret_cast<uint32_t*>(&hb);
        *(uint2*)(g_xh + (size_t)t * DDIM + i4) = o;
    }

    int w = threadIdx.x >> 5, lane = threadIdx.x & 31;
    const float* wg = Wg + (size_t)w * DDIM;
    float acc = 0.f;
    #pragma unroll 8
    for (int i = lane; i < DDIM; i += 32) acc += xs[i] * wg[i];
    #pragma unroll
    for (int o = 16; o; o >>= 1) acc += __shfl_xor_sync(0xFFFFFFFFu, acc, o);
    if (lane == 0) sc[w] = acc;
    __syncthreads();
    if (threadIdx.x == 0) {
        int e0 = 0; float s0 = sc[0];
        #pragma unroll
        for (int e = 1; e < NEXP; e++)
            if (sc[e] > s0) { s0 = sc[e]; e0 = e; }
        int e1 = -1; float s1 = -1e30f;
        #pragma unroll
        for (int e = 0; e < NEXP; e++)
            if (e != e0 && sc[e] > s1) { s1 = sc[e]; e1 = e; }
        float z = expf(s1 - s0);
        float inv = 1.f / (1.f + z);
        g_topE[2 * t] = e0;  g_topE[2 * t + 1] = e1;
        g_probs[2 * t] = inv; g_probs[2 * t + 1] = z * inv;
        atomicAdd(&g_counts[e0], 1);
        atomicAdd(&g_counts[e1], 1);
    }
}

// ---------------------------------------------------------------------------
// Scatter (with local scan of the 8 expert counts); records per-row token+prob
// ---------------------------------------------------------------------------
__global__ __launch_bounds__(256) void scatter_kernel() {
    __shared__ int soff[NEXP];
    if (threadIdx.x < NEXP) {
        int o = 0;
        for (int e = 0; e < threadIdx.x; e++) o += g_counts[e];
        soff[threadIdx.x] = o;
        if (blockIdx.x == 0) {
            g_offsets[threadIdx.x] = o;
            if (threadIdx.x == NEXP - 1) g_offsets[NEXP] = o + g_counts[NEXP - 1];
        }
    }
    __syncthreads();
    int t = blockIdx.x * blockDim.x + threadIdx.x;
    if (t >= TKN) return;
    #pragma unroll
    for (int k = 0; k < 2; k++) {
        int e = g_topE[2 * t + k];
        int pos = soff[e] + atomicAdd(&g_cursor[e], 1);
        g_rowTok[pos]  = t;
        g_rowProb[pos] = g_probs[2 * t + k];
    }
}

// ---------------------------------------------------------------------------
// Zero the output buffer (it is poisoned before timing)
// ---------------------------------------------------------------------------
__global__ __launch_bounds__(256) void zero_out_kernel(float* __restrict__ out) {
    int i = blockIdx.x * 256 + threadIdx.x;
    ((float4*)out)[i] = make_float4(0.f, 0.f, 0.f, 0.f);
}

// ---------------------------------------------------------------------------
// GEMM tile geometry: 256 threads (8 warps, 4x2), 2 CTAs/SM.
//   K_TILE = 64 halves (128 B + 16 pad -> 144 B row stride), 3 stages.
// ---------------------------------------------------------------------------
#define KT      64
#define RSTRB   144
#define G_SA    (128 * RSTRB)
#define STAGE   (2 * G_SA)             // 36864
#define SMEM_DYN (3 * STAGE)           // 110592

// ---------------------------------------------------------------------------
// GEMM1 + SwiGLU. BM=128 rows, BF=64 f-cols (x2 matrices). Warp: 32 x 32 x2.
// ---------------------------------------------------------------------------
__global__ __launch_bounds__(256, 2)
void gemm1_kernel() {
    int e = blockIdx.z;
    int cnt = g_counts[e];
    int base = blockIdx.y * 128;
    if (base >= cnt) return;
    int off = g_offsets[e];
    int f0 = blockIdx.x * 64;

    extern __shared__ char sm[];
    __shared__ int toks[128];
    int tid = threadIdx.x;
    if (tid < 128)
        toks[tid] = (base + tid < cnt) ? g_rowTok[off + base + tid] : -1;
    __syncthreads();

    const __half* W1e = g_W1h + ((size_t)e * FDIM + f0) * DDIM;
    const __half* W2e = g_W2h + ((size_t)e * FDIM + f0) * DDIM;

    int w = tid >> 5, lane = tid & 31;
    int wm = w >> 1, wn = w & 1;
    int g = lane >> 2, tig = lane & 3;

    uint32_t smbase = smem_u32(sm);
    uint32_t arow  = (uint32_t)((wm * 32 + (lane & 15)) * RSTRB + (lane >> 4) * 16);
    uint32_t brow4 = (uint32_t)((wn * 32 + (lane & 7) + ((lane >> 4) & 1) * 8) * RSTRB
                                + ((lane >> 3) & 1) * 16);

    float acc1[2][4][4], acc2[2][4][4];
    #pragma unroll
    for (int mi = 0; mi < 2; mi++)
        #pragma unroll
        for (int ni = 0; ni < 4; ni++)
            #pragma unroll
            for (int q = 0; q < 4; q++) { acc1[mi][ni][q] = 0.f; acc2[mi][ni][q] = 0.f; }

    const int NKT = DDIM / KT;   // 16

    auto load_stage = [&](int s, int k0) {
        char* smA = sm + s * STAGE;
        char* smB = smA + G_SA;
        #pragma unroll
        for (int j = 0; j < 4; j++) {
            int slot = tid + j * 256;
            int row = slot >> 3, q = slot & 7;
            int tok = toks[row];
            const __half* src = g_xh + (size_t)(tok >= 0 ? tok : 0) * DDIM + k0 + q * 8;
            cp16(smA + row * RSTRB + q * 16, src, tok >= 0 ? 16 : 0);
        }
        #pragma unroll
        for (int j = 0; j < 4; j++) {
            int slot = tid + j * 256;
            int r = slot >> 3, q = slot & 7;
            int mat = r >> 6, rw = r & 63;
            const __half* src = (mat ? W2e : W1e) + (size_t)rw * DDIM + k0 + q * 8;
            cp16(smB + r * RSTRB + q * 16, src, 16);
        }
    };

    load_stage(0, 0);  CP_COMMIT();
    load_stage(1, KT); CP_COMMIT();

    for (int kt = 0; kt < NKT; kt++) {
        if (kt + 1 < NKT) CP_WAIT(1); else CP_WAIT(0);
        __syncthreads();

        int s = kt % 3;
        uint32_t sa = smbase + s * STAGE;
        uint32_t ub = sa + G_SA;

        #pragma unroll
        for (int ks = 0; ks < 4; ks++) {
            uint32_t a0[4], a1[4], b1f[2][4], b2f[2][4];
            ldsm4(a0, sa + arow + ks * 32);
            ldsm4(a1, sa + arow + 16 * RSTRB + ks * 32);
            #pragma unroll
            for (int n2 = 0; n2 < 2; n2++) {
                ldsm4(b1f[n2], ub + brow4 + n2 * 16 * RSTRB + ks * 32);
                ldsm4(b2f[n2], ub + brow4 + (64 + n2 * 16) * RSTRB + ks * 32);
            }
            #pragma unroll
            for (int n2 = 0; n2 < 2; n2++) {
                #pragma unroll
                for (int h = 0; h < 2; h++) {
                    mma_f16(acc1[0][n2 * 2 + h], a0, b1f[n2][2 * h], b1f[n2][2 * h + 1]);
                    mma_f16(acc1[1][n2 * 2 + h], a1, b1f[n2][2 * h], b1f[n2][2 * h + 1]);
                    mma_f16(acc2[0][n2 * 2 + h], a0, b2f[n2][2 * h], b2f[n2][2 * h + 1]);
                    mma_f16(acc2[1][n2 * 2 + h], a1, b2f[n2][2 * h], b2f[n2][2 * h + 1]);
                }
            }
        }

        if (kt + 2 < NKT) { load_stage((kt + 2) % 3, (kt + 2) * KT); CP_COMMIT(); }
    }

    // Epilogue: SwiGLU -> Hh (fp16)
    #pragma unroll
    for (int mi = 0; mi < 2; mi++) {
        int r0 = base + wm * 32 + mi * 16 + g;
        #pragma unroll
        for (int ni = 0; ni < 4; ni++) {
            int col = f0 + wn * 32 + ni * 8 + tig * 2;
            #pragma unroll
            for (int half = 0; half < 2; half++) {
                int row = r0 + half * 8;
                if (row < cnt) {
                    float h1a = acc1[mi][ni][half * 2 + 0];
                    float h1b = acc1[mi][ni][half * 2 + 1];
                    float h2a = acc2[mi][ni][half * 2 + 0];
                    float h2b = acc2[mi][ni][half * 2 + 1];
                    float oa = h1a / (1.f + __expf(-h1a)) * h2a;
                    float ob = h1b / (1.f + __expf(-h1b)) * h2b;
                    *(__half2*)(g_Hh + (size_t)(off + row) * FDIM + col) =
                        __floats2half2_rn(oa, ob);
                }
            }
        }
    }
}

// ---------------------------------------------------------------------------
// GEMM2 + fused combine: out[tok] += prob * (H[row] . W3[e]^T)
// ---------------------------------------------------------------------------
__global__ __launch_bounds__(256, 2)
void gemm2_kernel(float* __restrict__ out) {
    int e = blockIdx.z;
    int cnt = g_counts[e];
    int base = blockIdx.y * 128;
    if (base >= cnt) return;
    int off = g_offsets[e];
    int d0 = blockIdx.x * 128;

    extern __shared__ char sm[];
    int tid = threadIdx.x;

    const __half* W3e = g_W3h + ((size_t)e * DDIM + d0) * FDIM;
    const __half* Ab  = g_Hh + (size_t)(off + base) * FDIM;
    int arows = cnt - base;

    int w = tid >> 5, lane = tid & 31;
    int wm = w >> 1, wn = w & 1;
    int g = lane >> 2, tig = lane & 3;

    uint32_t smbase = smem_u32(sm);
    uint32_t arow  = (uint32_t)((wm * 32 + (lane & 15)) * RSTRB + (lane >> 4) * 16);
    uint32_t brow4 = (uint32_t)((wn * 64 + (lane & 7) + ((lane >> 4) & 1) * 8) * RSTRB
                                + ((lane >> 3) & 1) * 16);

    float acc[2][8][4];
    #pragma unroll
    for (int mi = 0; mi < 2; mi++)
        #pragma unroll
        for (int ni = 0; ni < 8; ni++)
            #pragma unroll
            for (int q = 0; q < 4; q++) acc[mi][ni][q] = 0.f;

    const int NKT = FDIM / KT;   // 32

    auto load_stage = [&](int s, int k0) {
        char* smA = sm + s * STAGE;
        char* smB = smA + G_SA;
        #pragma unroll
        for (int j = 0; j < 4; j++) {
            int slot = tid + j * 256;
            int row = slot >> 3, q = slot & 7;
            const __half* src = Ab + (size_t)(row < arows ? row : 0) * FDIM + k0 + q * 8;
            cp16(smA + row * RSTRB + q * 16, src, row < arows ? 16 : 0);
        }
        #pragma unroll
        for (int j = 0; j < 4; j++) {
            int slot = tid + j * 256;
            int r = slot >> 3, q = slot & 7;
            const __half* src = W3e + (size_t)r * FDIM + k0 + q * 8;
            cp16(smB + r * RSTRB + q * 16, src, 16);
        }
    };

    load_stage(0, 0);  CP_COMMIT();
    load_stage(1, KT); CP_COMMIT();

    for (int kt = 0; kt < NKT; kt++) {
        if (kt + 1 < NKT) CP_WAIT(1); else CP_WAIT(0);
        __syncthreads();

        int s = kt % 3;
        uint32_t sa = smbase + s * STAGE;
        uint32_t ub = sa + G_SA;

        #pragma unroll
        for (int ks = 0; ks < 4; ks++) {
            uint32_t a0[4], a1[4], bf[4][4];
            ldsm4(a0, sa + arow + ks * 32);
            ldsm4(a1, sa + arow + 16 * RSTRB + ks * 32);
            #pragma unroll
            for (int n2 = 0; n2 < 4; n2++)
                ldsm4(bf[n2], ub + brow4 + n2 * 16 * RSTRB + ks * 32);
            #pragma unroll
            for (int n2 = 0; n2 < 4; n2++) {
                #pragma unroll
                for (int h = 0; h < 2; h++) {
                    mma_f16(acc[0][n2 * 2 + h], a0, bf[n2][2 * h], bf[n2][2 * h + 1]);
                    mma_f16(acc[1][n2 * 2 + h], a1, bf[n2][2 * h], bf[n2][2 * h + 1]);
                }
            }
        }

        if (kt + 2 < NKT) { load_stage((kt + 2) % 3, (kt + 2) * KT); CP_COMMIT(); }
    }

    // Fused combine epilogue: scale by gate prob, atomicAdd into out[token]
    #pragma unroll
    for (int mi = 0; mi < 2; mi++) {
        int rb = wm * 32 + mi * 16 + g;
        #pragma unroll
        for (int half = 0; half < 2; half++) {
            int row = base + rb + half * 8;
            if (row < cnt) {
                int   tok = g_rowTok[off + row];
                float p   = g_rowProb[off + row];
                float* op = out + (size_t)tok * DDIM + d0;
                #pragma unroll
                for (int ni = 0; ni < 8; ni++) {
                    int col = wn * 64 + ni * 8 + tig * 2;
                    atomicAdd(op + col,     p * acc[mi][ni][half * 2 + 0]);
                    atomicAdd(op + col + 1, p * acc[mi][ni][half * 2 + 1]);
                }
            }
        }
    }
}

// ---------------------------------------------------------------------------
// Entry point — forked side stream hides the weight converts + zero-fill:
//   side:  convert_w12 --ev1--> convert_w3, zero_out --ev2-->
//   main:  reset, gating(x->fp16 fused), scatter, [ev1] gemm1, [ev2] gemm2
// ---------------------------------------------------------------------------
extern "C" void kernel_launch(void* const* d_in, const int* in_sizes, int n_in,
                              void* d_out, int out_size) {
    (void)in_sizes; (void)n_in; (void)out_size;
    const float* x  = (const float*)d_in[0];
    const float* Wg = (const float*)d_in[1];
    const float* W1 = (const float*)d_in[2];
    const float* W2 = (const float*)d_in[3];
    const float* W3 = (const float*)d_in[4];
    float* out = (float*)d_out;

    cudaFuncSetAttribute(gemm1_kernel, cudaFuncAttributeMaxDynamicSharedMemorySize, SMEM_DYN);
    cudaFuncSetAttribute(gemm2_kernel, cudaFuncAttributeMaxDynamicSharedMemorySize, SMEM_DYN);

    cudaStream_t s1;
    cudaStreamCreateWithFlags(&s1, cudaStreamNonBlocking);
    cudaEvent_t ev0, ev1, ev2;
    cudaEventCreateWithFlags(&ev0, cudaEventDisableTiming);
    cudaEventCreateWithFlags(&ev1, cudaEventDisableTiming);
    cudaEventCreateWithFlags(&ev2, cudaEventDisableTiming);

    // Fork side stream from the main (capture) stream
    cudaEventRecord(ev0, 0);
    cudaStreamWaitEvent(s1, ev0, 0);

    // Side stream: weight converts + output zero-fill
    convert_w12_kernel<<<(int)(2 * WP / 512), 256, 0, s1>>>(W1, W2);
    cudaEventRecord(ev1, s1);
    convert_w3_kernel<<<(int)(WP / 512), 256, 0, s1>>>(W3);
    zero_out_kernel<<<TKN * DDIM / 1024, 256, 0, s1>>>(out);
    cudaEventRecord(ev2, s1);

    // Main stream: routing path
    reset_kernel<<<1, 32>>>();
    gating_kernel<<<TKN, 256>>>(x, Wg);
    scatter_kernel<<<TKN / 256, 256>>>();

    cudaStreamWaitEvent(0, ev1, 0);   // gemm1 needs W1h/W2h
    gemm1_kernel<<<dim3(FDIM / 64, TKN / 128, NEXP), 256, SMEM_DYN>>>();

    cudaStreamWaitEvent(0, ev2, 0);   // gemm2 needs W3h + zeroed out
    gemm2_kernel<<<dim3(DDIM / 128, TKN / 128, NEXP), 256, SMEM_DYN>>>(out);
}

// round 11
// speedup vs baseline: 3.2065x; 1.0163x over previous
#include <cuda_runtime.h>
#include <cuda_fp16.h>
#include <cstdint>
#include <math.h>

// Problem constants
#define TKN   4096
#define DDIM  1024
#define FDIM  2048
#define NEXP  8
#define NASS  (TKN * 2)

// ---------------------------------------------------------------------------
// Scratch (device globals)
// ---------------------------------------------------------------------------
__device__ int   g_counts[NEXP];
__device__ int   g_offsets[NEXP + 1];
__device__ int   g_cursor[NEXP];
__device__ int   g_rowTok[NASS];
__device__ float g_rowProb[NASS];
__device__ float g_probs[NASS];
__device__ int   g_topE[NASS];

__device__ __align__(16) __half g_xh[(size_t)TKN * DDIM];
__device__ __align__(16) __half g_W1h[(size_t)NEXP * FDIM * DDIM];
__device__ __align__(16) __half g_W2h[(size_t)NEXP * FDIM * DDIM];
__device__ __align__(16) __half g_W3h[(size_t)NEXP * DDIM * FDIM];
__device__ __align__(16) __half g_Hh[(size_t)NASS * FDIM];

// ---------------------------------------------------------------------------
// Helpers
// ---------------------------------------------------------------------------
__device__ __forceinline__ uint32_t smem_u32(const void* p) {
    uint32_t a;
    asm("{ .reg .u64 t; cvta.to.shared.u64 t, %1; cvt.u32.u64 %0, t; }" : "=r"(a) : "l"(p));
    return a;
}
__device__ __forceinline__ void cp16(void* dst, const void* src, int zfill) {
    uint32_t d = smem_u32(dst);
    asm volatile("cp.async.cg.shared.global [%0], [%1], 16, %2;"
                 :: "r"(d), "l"(src), "r"(zfill) : "memory");
}
#define CP_COMMIT() asm volatile("cp.async.commit_group;" ::: "memory")
#define CP_WAIT(n)  asm volatile("cp.async.wait_group %0;" :: "n"(n) : "memory")

__device__ __forceinline__ void mma_f16(float* c, const uint32_t* a,
                                        uint32_t b0, uint32_t b1) {
    asm volatile(
        "mma.sync.aligned.m16n8k16.row.col.f32.f16.f16.f32 "
        "{%0,%1,%2,%3}, {%4,%5,%6,%7}, {%8,%9}, {%0,%1,%2,%3};"
        : "+f"(c[0]), "+f"(c[1]), "+f"(c[2]), "+f"(c[3])
        : "r"(a[0]), "r"(a[1]), "r"(a[2]), "r"(a[3]), "r"(b0), "r"(b1));
}
__device__ __forceinline__ void ldsm4(uint32_t* r, uint32_t a) {
    asm volatile("ldmatrix.sync.aligned.m8n8.x4.shared.b16 {%0,%1,%2,%3}, [%4];"
                 : "=r"(r[0]), "=r"(r[1]), "=r"(r[2]), "=r"(r[3]) : "r"(a));
}

// ---------------------------------------------------------------------------
// Weight converts (pair granularity: 2 float4 loads -> 1 uint4 store)
// ---------------------------------------------------------------------------
#define W4 (NEXP * FDIM * DDIM / 4)
#define WP ((long)W4 / 2)

__device__ __forceinline__ void cvt_pair(const float4* s, uint4* d, long j) {
    float4 a = s[2 * j], b = s[2 * j + 1];
    __half2 h0 = __floats2half2_rn(a.x, a.y);
    __half2 h1 = __floats2half2_rn(a.z, a.w);
    __half2 h2 = __floats2half2_rn(b.x, b.y);
    __half2 h3 = __floats2half2_rn(b.z, b.w);
    uint4 o;
    o.x = *reinterpret_cast<uint32_t*>(&h0);
    o.y = *reinterpret_cast<uint32_t*>(&h1);
    o.z = *reinterpret_cast<uint32_t*>(&h2);
    o.w = *reinterpret_cast<uint32_t*>(&h3);
    d[j] = o;
}

__global__ __launch_bounds__(256) void convert_w12_kernel(
    const float* __restrict__ W1, const float* __restrict__ W2) {
    #pragma unroll
    for (int u = 0; u < 2; u++) {
        long p = (long)blockIdx.x * 512 + u * 256 + threadIdx.x;
        if (p < WP)           cvt_pair((const float4*)W1, (uint4*)g_W1h, p);
        else if (p < 2 * WP)  cvt_pair((const float4*)W2, (uint4*)g_W2h, p - WP);
    }
}

__global__ __launch_bounds__(256) void convert_w3_kernel(const float* __restrict__ W3) {
    #pragma unroll
    for (int u = 0; u < 2; u++) {
        long p = (long)blockIdx.x * 512 + u * 256 + threadIdx.x;
        if (p < WP) cvt_pair((const float4*)W3, (uint4*)g_W3h, p);
    }
}

// ---------------------------------------------------------------------------
// Reset routing counters
// ---------------------------------------------------------------------------
__global__ void reset_kernel() {
    if (threadIdx.x < NEXP) {
        g_counts[threadIdx.x] = 0;
        g_cursor[threadIdx.x] = 0;
    }
}

// ---------------------------------------------------------------------------
// Gating: top-2 + softmax + counts; ALSO converts this token's x row to fp16
// ---------------------------------------------------------------------------
__global__ __launch_bounds__(256) void gating_kernel(
    const float* __restrict__ x, const float* __restrict__ Wg) {
    int t = blockIdx.x;
    __shared__ float xs[DDIM];
    __shared__ float sc[NEXP];
    for (int i = threadIdx.x; i < DDIM; i += 256)
        xs[i] = x[(size_t)t * DDIM + i];
    __syncthreads();

    {
        int i4 = threadIdx.x * 4;
        __half2 ha = __floats2half2_rn(xs[i4],     xs[i4 + 1]);
        __half2 hb = __floats2half2_rn(xs[i4 + 2], xs[i4 + 3]);
        uint2 o;
        o.x = *reinterpret_cast<uint32_t*>(&ha);
        o.y = *reinterpret_cast<uint32_t*>(&hb);
        *(uint2*)(g_xh + (size_t)t * DDIM + i4) = o;
    }

    int w = threadIdx.x >> 5, lane = threadIdx.x & 31;
    const float* wg = Wg + (size_t)w * DDIM;
    float acc = 0.f;
    #pragma unroll 8
    for (int i = lane; i < DDIM; i += 32) acc += xs[i] * wg[i];
    #pragma unroll
    for (int o = 16; o; o >>= 1) acc += __shfl_xor_sync(0xFFFFFFFFu, acc, o);
    if (lane == 0) sc[w] = acc;
    __syncthreads();
    if (threadIdx.x == 0) {
        int e0 = 0; float s0 = sc[0];
        #pragma unroll
        for (int e = 1; e < NEXP; e++)
            if (sc[e] > s0) { s0 = sc[e]; e0 = e; }
        int e1 = -1; float s1 = -1e30f;
        #pragma unroll
        for (int e = 0; e < NEXP; e++)
            if (e != e0 && sc[e] > s1) { s1 = sc[e]; e1 = e; }
        float z = expf(s1 - s0);
        float inv = 1.f / (1.f + z);
        g_topE[2 * t] = e0;  g_topE[2 * t + 1] = e1;
        g_probs[2 * t] = inv; g_probs[2 * t + 1] = z * inv;
        atomicAdd(&g_counts[e0], 1);
        atomicAdd(&g_counts[e1], 1);
    }
}

// ---------------------------------------------------------------------------
// Scatter (with local scan of the 8 expert counts); records per-row token+prob
// ---------------------------------------------------------------------------
__global__ __launch_bounds__(256) void scatter_kernel() {
    __shared__ int soff[NEXP];
    if (threadIdx.x < NEXP) {
        int o = 0;
        for (int e = 0; e < threadIdx.x; e++) o += g_counts[e];
        soff[threadIdx.x] = o;
        if (blockIdx.x == 0) {
            g_offsets[threadIdx.x] = o;
            if (threadIdx.x == NEXP - 1) g_offsets[NEXP] = o + g_counts[NEXP - 1];
        }
    }
    __syncthreads();
    int t = blockIdx.x * blockDim.x + threadIdx.x;
    if (t >= TKN) return;
    #pragma unroll
    for (int k = 0; k < 2; k++) {
        int e = g_topE[2 * t + k];
        int pos = soff[e] + atomicAdd(&g_cursor[e], 1);
        g_rowTok[pos]  = t;
        g_rowProb[pos] = g_probs[2 * t + k];
    }
}

// ---------------------------------------------------------------------------
// Zero the output buffer (it is poisoned before timing)
// ---------------------------------------------------------------------------
__global__ __launch_bounds__(256) void zero_out_kernel(float* __restrict__ out) {
    int i = blockIdx.x * 256 + threadIdx.x;
    ((float4*)out)[i] = make_float4(0.f, 0.f, 0.f, 0.f);
}

// ---------------------------------------------------------------------------
// GEMM tile geometry: 256 threads (8 warps, 4x2), 2 CTAs/SM.
//   K_TILE = 64 halves (128 B + 16 pad -> 144 B row stride), 3 stages.
// ---------------------------------------------------------------------------
#define KT      64
#define RSTRB   144
#define G_SA    (128 * RSTRB)
#define STAGE   (2 * G_SA)             // 36864
#define SMEM_DYN (3 * STAGE)           // 110592

// ---------------------------------------------------------------------------
// GEMM1 + SwiGLU. BM=128 rows, BF=64 f-cols (x2 matrices). Warp: 32 x 32 x2.
// ebase selects the expert group (blockIdx.z + ebase).
// ---------------------------------------------------------------------------
__global__ __launch_bounds__(256, 2)
void gemm1_kernel(int ebase) {
    int e = blockIdx.z + ebase;
    int cnt = g_counts[e];
    int base = blockIdx.y * 128;
    if (base >= cnt) return;
    int off = g_offsets[e];
    int f0 = blockIdx.x * 64;

    extern __shared__ char sm[];
    __shared__ int toks[128];
    int tid = threadIdx.x;
    if (tid < 128)
        toks[tid] = (base + tid < cnt) ? g_rowTok[off + base + tid] : -1;
    __syncthreads();

    const __half* W1e = g_W1h + ((size_t)e * FDIM + f0) * DDIM;
    const __half* W2e = g_W2h + ((size_t)e * FDIM + f0) * DDIM;

    int w = tid >> 5, lane = tid & 31;
    int wm = w >> 1, wn = w & 1;
    int g = lane >> 2, tig = lane & 3;

    uint32_t smbase = smem_u32(sm);
    uint32_t arow  = (uint32_t)((wm * 32 + (lane & 15)) * RSTRB + (lane >> 4) * 16);
    uint32_t brow4 = (uint32_t)((wn * 32 + (lane & 7) + ((lane >> 4) & 1) * 8) * RSTRB
                                + ((lane >> 3) & 1) * 16);

    float acc1[2][4][4], acc2[2][4][4];
    #pragma unroll
    for (int mi = 0; mi < 2; mi++)
        #pragma unroll
        for (int ni = 0; ni < 4; ni++)
            #pragma unroll
            for (int q = 0; q < 4; q++) { acc1[mi][ni][q] = 0.f; acc2[mi][ni][q] = 0.f; }

    const int NKT = DDIM / KT;   // 16

    auto load_stage = [&](int s, int k0) {
        char* smA = sm + s * STAGE;
        char* smB = smA + G_SA;
        #pragma unroll
        for (int j = 0; j < 4; j++) {
            int slot = tid + j * 256;
            int row = slot >> 3, q = slot & 7;
            int tok = toks[row];
            const __half* src = g_xh + (size_t)(tok >= 0 ? tok : 0) * DDIM + k0 + q * 8;
            cp16(smA + row * RSTRB + q * 16, src, tok >= 0 ? 16 : 0);
        }
        #pragma unroll
        for (int j = 0; j < 4; j++) {
            int slot = tid + j * 256;
            int r = slot >> 3, q = slot & 7;
            int mat = r >> 6, rw = r & 63;
            const __half* src = (mat ? W2e : W1e) + (size_t)rw * DDIM + k0 + q * 8;
            cp16(smB + r * RSTRB + q * 16, src, 16);
        }
    };

    load_stage(0, 0);  CP_COMMIT();
    load_stage(1, KT); CP_COMMIT();

    for (int kt = 0; kt < NKT; kt++) {
        if (kt + 1 < NKT) CP_WAIT(1); else CP_WAIT(0);
        __syncthreads();

        int s = kt % 3;
        uint32_t sa = smbase + s * STAGE;
        uint32_t ub = sa + G_SA;

        #pragma unroll
        for (int ks = 0; ks < 4; ks++) {
            uint32_t a0[4], a1[4], b1f[2][4], b2f[2][4];
            ldsm4(a0, sa + arow + ks * 32);
            ldsm4(a1, sa + arow + 16 * RSTRB + ks * 32);
            #pragma unroll
            for (int n2 = 0; n2 < 2; n2++) {
                ldsm4(b1f[n2], ub + brow4 + n2 * 16 * RSTRB + ks * 32);
                ldsm4(b2f[n2], ub + brow4 + (64 + n2 * 16) * RSTRB + ks * 32);
            }
            #pragma unroll
            for (int n2 = 0; n2 < 2; n2++) {
                #pragma unroll
                for (int h = 0; h < 2; h++) {
                    mma_f16(acc1[0][n2 * 2 + h], a0, b1f[n2][2 * h], b1f[n2][2 * h + 1]);
                    mma_f16(acc1[1][n2 * 2 + h], a1, b1f[n2][2 * h], b1f[n2][2 * h + 1]);
                    mma_f16(acc2[0][n2 * 2 + h], a0, b2f[n2][2 * h], b2f[n2][2 * h + 1]);
                    mma_f16(acc2[1][n2 * 2 + h], a1, b2f[n2][2 * h], b2f[n2][2 * h + 1]);
                }
            }
        }

        if (kt + 2 < NKT) { load_stage((kt + 2) % 3, (kt + 2) * KT); CP_COMMIT(); }
    }

    // Epilogue: SwiGLU -> Hh (fp16)
    #pragma unroll
    for (int mi = 0; mi < 2; mi++) {
        int r0 = base + wm * 32 + mi * 16 + g;
        #pragma unroll
        for (int ni = 0; ni < 4; ni++) {
            int col = f0 + wn * 32 + ni * 8 + tig * 2;
            #pragma unroll
            for (int half = 0; half < 2; half++) {
                int row = r0 + half * 8;
                if (row < cnt) {
                    float h1a = acc1[mi][ni][half * 2 + 0];
                    float h1b = acc1[mi][ni][half * 2 + 1];
                    float h2a = acc2[mi][ni][half * 2 + 0];
                    float h2b = acc2[mi][ni][half * 2 + 1];
                    float oa = h1a / (1.f + __expf(-h1a)) * h2a;
                    float ob = h1b / (1.f + __expf(-h1b)) * h2b;
                    *(__half2*)(g_Hh + (size_t)(off + row) * FDIM + col) =
                        __floats2half2_rn(oa, ob);
                }
            }
        }
    }
}

// ---------------------------------------------------------------------------
// GEMM2 + fused combine: out[tok] += prob * (H[row] . W3[e]^T)
// ---------------------------------------------------------------------------
__global__ __launch_bounds__(256, 2)
void gemm2_kernel(float* __restrict__ out, int ebase) {
    int e = blockIdx.z + ebase;
    int cnt = g_counts[e];
    int base = blockIdx.y * 128;
    if (base >= cnt) return;
    int off = g_offsets[e];
    int d0 = blockIdx.x * 128;

    extern __shared__ char sm[];
    int tid = threadIdx.x;

    const __half* W3e = g_W3h + ((size_t)e * DDIM + d0) * FDIM;
    const __half* Ab  = g_Hh + (size_t)(off + base) * FDIM;
    int arows = cnt - base;

    int w = tid >> 5, lane = tid & 31;
    int wm = w >> 1, wn = w & 1;
    int g = lane >> 2, tig = lane & 3;

    uint32_t smbase = smem_u32(sm);
    uint32_t arow  = (uint32_t)((wm * 32 + (lane & 15)) * RSTRB + (lane >> 4) * 16);
    uint32_t brow4 = (uint32_t)((wn * 64 + (lane & 7) + ((lane >> 4) & 1) * 8) * RSTRB
                                + ((lane >> 3) & 1) * 16);

    float acc[2][8][4];
    #pragma unroll
    for (int mi = 0; mi < 2; mi++)
        #pragma unroll
        for (int ni = 0; ni < 8; ni++)
            #pragma unroll
            for (int q = 0; q < 4; q++) acc[mi][ni][q] = 0.f;

    const int NKT = FDIM / KT;   // 32

    auto load_stage = [&](int s, int k0) {
        char* smA = sm + s * STAGE;
        char* smB = smA + G_SA;
        #pragma unroll
        for (int j = 0; j < 4; j++) {
            int slot = tid + j * 256;
            int row = slot >> 3, q = slot & 7;
            const __half* src = Ab + (size_t)(row < arows ? row : 0) * FDIM + k0 + q * 8;
            cp16(smA + row * RSTRB + q * 16, src, row < arows ? 16 : 0);
        }
        #pragma unroll
        for (int j = 0; j < 4; j++) {
            int slot = tid + j * 256;
            int r = slot >> 3, q = slot & 7;
            const __half* src = W3e + (size_t)r * FDIM + k0 + q * 8;
            cp16(smB + r * RSTRB + q * 16, src, 16);
        }
    };

    load_stage(0, 0);  CP_COMMIT();
    load_stage(1, KT); CP_COMMIT();

    for (int kt = 0; kt < NKT; kt++) {
        if (kt + 1 < NKT) CP_WAIT(1); else CP_WAIT(0);
        __syncthreads();

        int s = kt % 3;
        uint32_t sa = smbase + s * STAGE;
        uint32_t ub = sa + G_SA;

        #pragma unroll
        for (int ks = 0; ks < 4; ks++) {
            uint32_t a0[4], a1[4], bf[4][4];
            ldsm4(a0, sa + arow + ks * 32);
            ldsm4(a1, sa + arow + 16 * RSTRB + ks * 32);
            #pragma unroll
            for (int n2 = 0; n2 < 4; n2++)
                ldsm4(bf[n2], ub + brow4 + n2 * 16 * RSTRB + ks * 32);
            #pragma unroll
            for (int n2 = 0; n2 < 4; n2++) {
                #pragma unroll
                for (int h = 0; h < 2; h++) {
                    mma_f16(acc[0][n2 * 2 + h], a0, bf[n2][2 * h], bf[n2][2 * h + 1]);
                    mma_f16(acc[1][n2 * 2 + h], a1, bf[n2][2 * h], bf[n2][2 * h + 1]);
                }
            }
        }

        if (kt + 2 < NKT) { load_stage((kt + 2) % 3, (kt + 2) * KT); CP_COMMIT(); }
    }

    // Fused combine epilogue: scale by gate prob, atomicAdd into out[token]
    #pragma unroll
    for (int mi = 0; mi < 2; mi++) {
        int rb = wm * 32 + mi * 16 + g;
        #pragma unroll
        for (int half = 0; half < 2; half++) {
            int row = base + rb + half * 8;
            if (row < cnt) {
                int   tok = g_rowTok[off + row];
                float p   = g_rowProb[off + row];
                float* op = out + (size_t)tok * DDIM + d0;
                #pragma unroll
                for (int ni = 0; ni < 8; ni++) {
                    int col = wn * 64 + ni * 8 + tig * 2;
                    atomicAdd(op + col,     p * acc[mi][ni][half * 2 + 0]);
                    atomicAdd(op + col + 1, p * acc[mi][ni][half * 2 + 1]);
                }
            }
        }
    }
}

// ---------------------------------------------------------------------------
// Entry point — per-expert-group pipelining across two streams:
//   side: convert_w12 -(evW12)-> convert_w3, zero_out -(evZ)->
//         [evA] gemm2_lo -(evLo)->
//   main: reset, gating, scatter, [evW12] gemm1_lo -(evA)-> gemm1_hi,
//         [evZ] gemm2_hi, [evLo] join
// ---------------------------------------------------------------------------
extern "C" void kernel_launch(void* const* d_in, const int* in_sizes, int n_in,
                              void* d_out, int out_size) {
    (void)in_sizes; (void)n_in; (void)out_size;
    const float* x  = (const float*)d_in[0];
    const float* Wg = (const float*)d_in[1];
    const float* W1 = (const float*)d_in[2];
    const float* W2 = (const float*)d_in[3];
    const float* W3 = (const float*)d_in[4];
    float* out = (float*)d_out;

    cudaFuncSetAttribute(gemm1_kernel, cudaFuncAttributeMaxDynamicSharedMemorySize, SMEM_DYN);
    cudaFuncSetAttribute(gemm2_kernel, cudaFuncAttributeMaxDynamicSharedMemorySize, SMEM_DYN);

    cudaStream_t s1;
    cudaStreamCreateWithFlags(&s1, cudaStreamNonBlocking);
    cudaEvent_t ev0, evW12, evZ, evA, evLo;
    cudaEventCreateWithFlags(&ev0,   cudaEventDisableTiming);
    cudaEventCreateWithFlags(&evW12, cudaEventDisableTiming);
    cudaEventCreateWithFlags(&evZ,   cudaEventDisableTiming);
    cudaEventCreateWithFlags(&evA,   cudaEventDisableTiming);
    cudaEventCreateWithFlags(&evLo,  cudaEventDisableTiming);

    // Fork side stream from the main (capture) stream
    cudaEventRecord(ev0, 0);
    cudaStreamWaitEvent(s1, ev0, 0);

    // Side stream: weight converts + zero-fill
    convert_w12_kernel<<<(int)(2 * WP / 512), 256, 0, s1>>>(W1, W2);
    cudaEventRecord(evW12, s1);
    convert_w3_kernel<<<(int)(WP / 512), 256, 0, s1>>>(W3);
    zero_out_kernel<<<TKN * DDIM / 1024, 256, 0, s1>>>(out);
    cudaEventRecord(evZ, s1);

    // Main stream: routing
    reset_kernel<<<1, 32>>>();
    gating_kernel<<<TKN, 256>>>(x, Wg);
    scatter_kernel<<<TKN / 256, 256>>>();

    // gemm1 lo (experts 0-3), then hi (4-7) on main stream
    cudaStreamWaitEvent(0, evW12, 0);
    gemm1_kernel<<<dim3(FDIM / 64, TKN / 128, 4), 256, SMEM_DYN>>>(0);
    cudaEventRecord(evA, 0);
    gemm1_kernel<<<dim3(FDIM / 64, TKN / 128, 4), 256, SMEM_DYN>>>(4);

    // gemm2 lo on side stream, concurrent with gemm1 hi
    cudaStreamWaitEvent(s1, evA, 0);
    gemm2_kernel<<<dim3(DDIM / 128, TKN / 128, 4), 256, SMEM_DYN, s1>>>(out, 0);
    cudaEventRecord(evLo, s1);

    // gemm2 hi on main stream (after gemm1 hi, needs W3h + zeroed out)
    cudaStreamWaitEvent(0, evZ, 0);
    gemm2_kernel<<<dim3(DDIM / 128, TKN / 128, 4), 256, SMEM_DYN>>>(out, 4);

    // Join side stream back into capture origin
    cudaStreamWaitEvent(0, evLo, 0);
}